// round 4
// baseline (speedup 1.0000x reference)
#include <cuda_runtime.h>
#include <cuda_bf16.h>
#include <cstdint>
#include <math.h>

#define BDIM 64
#define TDIM 768
#define DDIM 128
#define EDIM 64
#define HDIM 128
#define ODIM 10
#define TC   256
#define G4   512
#define EPSP 5.0f

// ---------------- device scratch (no allocation allowed) ----------------
__device__ __align__(16) float g_emb[BDIM * TC * EDIM];     // conv output pre-BN [row][e]
__device__ __align__(16) float g_zx[(size_t)BDIM * TC * G4];// x-part gate preacts [row][512]
__device__ __align__(16) float g_whhT[HDIM * G4];           // [h][j]
__device__ __align__(16) float g_wihT[EDIM * G4];           // [e][j]
__device__ __align__(16) float g_convW[384 * EDIM];         // [(k*128+d)][e]
__device__ __align__(16) float g_bias[G4];                  // b_ih + b_hh
__device__ float g_part_s[256 * EDIM];
__device__ float g_part_ss[256 * EDIM];
__device__ float g_scale[EDIM];
__device__ float g_shift[EDIM];

__device__ __forceinline__ float sigf(float x) {
    return 1.0f / (1.0f + expf(-x));
}

// ---------------- K0: weight transposes + fused bias ----------------
__global__ __launch_bounds__(256) void k0_prep(
    const float* __restrict__ wih, const float* __restrict__ whh,
    const float* __restrict__ bih, const float* __restrict__ bhh,
    const float* __restrict__ conv_w) {
    int i = blockIdx.x * 256 + threadIdx.x;
    if (i < 65536) {                      // whhT[h][j] = whh[j][h]
        int h = i >> 9, j = i & 511;
        g_whhT[i] = whh[j * HDIM + h];
    } else if (i < 65536 + 32768) {       // wihT[e][j] = wih[j][e]
        int m = i - 65536;
        int e = m >> 9, j = m & 511;
        g_wihT[m] = wih[j * EDIM + e];
    } else if (i < 65536 + 32768 + 24576) { // convW[(k*128+d)][e] = conv_w[e][d][k]
        int m = i - 65536 - 32768;
        int q = m >> 6, e = m & 63;
        int k = q >> 7, d = q & 127;
        g_convW[m] = conv_w[e * 384 + d * 3 + k];
    } else if (i < 65536 + 32768 + 24576 + 512) {
        int j = i - 65536 - 32768 - 24576;
        g_bias[j] = bih[j] + bhh[j];
    }
}

// ---------------- K1: L2-normalize + Conv1d (non-overlapping => GEMM) ----------------
// grid = 64 b * 16 segs; block handles 16 conv rows (48 input rows)
__global__ __launch_bounds__(256) void k1_conv(
    const float* __restrict__ in, const float* __restrict__ conv_b) {
    __shared__ float xn[48 * 128];
    __shared__ float invn[48];
    int tid = threadIdx.x;
    int b = blockIdx.x >> 4, seg = blockIdx.x & 15;

    const float4* src = (const float4*)(in + ((size_t)b * TDIM + seg * 48) * DDIM);
    float4* d4 = (float4*)xn;
    for (int i = tid; i < 1536; i += 256) d4[i] = src[i];
    __syncthreads();

    int warp = tid >> 5, lane = tid & 31;
    for (int r = warp; r < 48; r += 8) {
        float v = 0.f;
        #pragma unroll
        for (int q = 0; q < 4; q++) { float x = xn[r * 128 + lane + q * 32]; v += x * x; }
        #pragma unroll
        for (int off = 16; off; off >>= 1) v += __shfl_down_sync(0xffffffffu, v, off);
        if (lane == 0) invn[r] = 1.0f / fmaxf(sqrtf(v), 1e-12f);
    }
    __syncthreads();
    for (int i = tid; i < 6144; i += 256) xn[i] *= invn[i >> 7];
    __syncthreads();

    // GEMM: 16 conv rows x 64 cols, contraction over 384
    int e = tid & 63, rg = tid >> 6;  // 4 row-groups of 4 rows
    float acc0 = 0.f, acc1 = 0.f, acc2 = 0.f, acc3 = 0.f;
    const float* xr = xn + rg * 4 * 384;
    for (int q = 0; q < 384; q++) {
        float wv = g_convW[q * 64 + e];
        acc0 += xr[q] * wv;
        acc1 += xr[q + 384] * wv;
        acc2 += xr[q + 768] * wv;
        acc3 += xr[q + 1152] * wv;
    }
    float cb = conv_b[e];
    int row0 = b * TC + seg * 16 + rg * 4;
    g_emb[(row0 + 0) * 64 + e] = acc0 + cb;
    g_emb[(row0 + 1) * 64 + e] = acc1 + cb;
    g_emb[(row0 + 2) * 64 + e] = acc2 + cb;
    g_emb[(row0 + 3) * 64 + e] = acc3 + cb;
}

// ---------------- K2a: BN partial sums (deterministic, no atomics) ----------------
__global__ __launch_bounds__(256) void k2a_stats() {
    __shared__ float ps[256], pss[256];
    int tid = threadIdx.x;
    int r0 = blockIdx.x * 64;
    int e = tid & 63, qr = tid >> 6;
    float s = 0.f, ss = 0.f;
    for (int u = 0; u < 16; u++) {
        float v = g_emb[(r0 + qr * 16 + u) * 64 + e];
        s += v; ss += v * v;
    }
    ps[tid] = s; pss[tid] = ss;
    __syncthreads();
    if (tid < 64) {
        s  = ps[tid]  + ps[tid + 64]  + ps[tid + 128]  + ps[tid + 192];
        ss = pss[tid] + pss[tid + 64] + pss[tid + 128] + pss[tid + 192];
        g_part_s[blockIdx.x * 64 + tid] = s;
        g_part_ss[blockIdx.x * 64 + tid] = ss;
    }
}

// ---------------- K2b: finalize BN scale/shift ----------------
__global__ __launch_bounds__(64) void k2b_finalize(
    const float* __restrict__ gamma, const float* __restrict__ beta) {
    int e = threadIdx.x;
    float s = 0.f, ss = 0.f;
    for (int blk = 0; blk < 256; blk++) {
        s  += g_part_s[blk * 64 + e];
        ss += g_part_ss[blk * 64 + e];
    }
    const float inv_n = 1.0f / 16384.0f;
    float mean = s * inv_n;
    float var = ss * inv_n - mean * mean;
    float sc = gamma[e] * rsqrtf(var + 1e-5f);
    g_scale[e] = sc;
    g_shift[e] = beta[e] - mean * sc;
}

// ---------------- K3: zx = ReLU(BN(emb)) @ wihT + bias ----------------
// grid 2048, each block 8 rows x 512 cols
__global__ __launch_bounds__(256) void k3_zx() {
    __shared__ float act[512];
    int tid = threadIdx.x;
    int r0 = blockIdx.x * 8;
    for (int i = tid; i < 512; i += 256) {
        int rr = i >> 6, e = i & 63;
        float a = g_emb[(r0 + rr) * 64 + e];
        act[i] = fmaxf(a * g_scale[e] + g_shift[e], 0.f);
    }
    __syncthreads();
    int j0 = tid, j1 = tid + 256;
    float acc0[8], acc1[8];
    float b0 = g_bias[j0], b1 = g_bias[j1];
    #pragma unroll
    for (int u = 0; u < 8; u++) { acc0[u] = b0; acc1[u] = b1; }
    for (int e = 0; e < 64; e++) {
        float w0 = g_wihT[e * 512 + j0];
        float w1 = g_wihT[e * 512 + j1];
        #pragma unroll
        for (int u = 0; u < 8; u++) {
            float a = act[u * 64 + e];
            acc0[u] += a * w0;
            acc1[u] += a * w1;
        }
    }
    #pragma unroll
    for (int u = 0; u < 8; u++) {
        float* zr = g_zx + ((size_t)(r0 + u)) * 512;
        zr[j0] = acc0[u];
        zr[j1] = acc1[u];
    }
}

// ---------------- K4: recurrent scan (one block per batch row) ----------------
// Woodbury: c = s - eps*G*(I + eps*G^T G)^{-1} G^T s,  G: [128][64]
#define GS_STRIDE 68
#define MS_STRIDE 65
__global__ __launch_bounds__(256) void k4_scan(
    const float* __restrict__ lin_w, const float* __restrict__ lin_b,
    const float* __restrict__ wih, float* __restrict__ out) {
    extern __shared__ float sm[];
    float* Gs  = sm;                 // 128*68 = 8704
    float* Ms  = sm + 8704;          // 64*65  = 4160
    float* Ln  = sm + 12864;         // 64*65  = 4160  (L natural: Ln[j][k] = L[j][k], j>k)
    float* i_s = sm + 17024;
    float* f_s = sm + 17152;
    float* gg_s= sm + 17280;
    float* o_s = sm + 17408;
    float* s_s = sm + 17536;
    float* ai  = sm + 17664;
    float* af  = sm + 17792;
    float* ag  = sm + 17920;
    float* h_sm= sm + 18048;
    float* c_sm= sm + 18176;
    float* wv  = sm + 18304;
    float* dinv= sm + 18368;         // end 18432 floats = 73728 B

    int tid = threadIdx.x;
    int b = blockIdx.x;

    if (tid < 128) { h_sm[tid] = 0.f; c_sm[tid] = 0.f; }
    __syncthreads();

    for (int t = 0; t < TC; t++) {
        // ---- z = zx + h @ whhT ; gates ----
        {
            const float* zrow = g_zx + ((size_t)(b * TC + t)) * 512;
            float a0 = zrow[tid], a1 = zrow[tid + 256];
            #pragma unroll 4
            for (int hh = 0; hh < 128; hh += 4) {
                float h0 = h_sm[hh], h1 = h_sm[hh + 1], h2 = h_sm[hh + 2], h3 = h_sm[hh + 3];
                const float* wp = g_whhT + hh * 512 + tid;
                a0 += h0 * wp[0];    a1 += h0 * wp[256];
                a0 += h1 * wp[512];  a1 += h1 * wp[768];
                a0 += h2 * wp[1024]; a1 += h2 * wp[1280];
                a0 += h3 * wp[1536]; a1 += h3 * wp[1792];
            }
            if (tid < 128) { i_s[tid] = sigf(a0); gg_s[tid] = tanhf(a1); }
            else           { f_s[tid - 128] = sigf(a0); o_s[tid - 128] = sigf(a1); }
        }
        __syncthreads();

        // ---- s and Jacobian row coefficients ----
        if (tid < 128) {
            float iv = i_s[tid], fv = f_s[tid], gv = gg_s[tid], cv = c_sm[tid];
            s_s[tid] = fv * cv + iv * gv;
            ai[tid] = iv * (1.f - iv) * gv;
            af[tid] = fv * (1.f - fv) * cv;
            ag[tid] = iv * (1.f - gv * gv);
        }
        __syncthreads();

        // ---- G[h][e] = ai*Wi + af*Wf + ag*Wg ----
        {
            int e = tid & 63, hg = tid >> 6;
            #pragma unroll 4
            for (int u = 0; u < 32; u++) {
                int h = hg * 32 + u;
                float g = ai[h] * wih[h * 64 + e]
                        + af[h] * wih[(128 + h) * 64 + e]
                        + ag[h] * wih[(256 + h) * 64 + e];
                Gs[h * GS_STRIDE + e] = g;
            }
        }
        __syncthreads();

        // ---- M = I + eps*G^T G (4x4 register tiles) ----
        {
            int tp = tid >> 4, tq = tid & 15;
            int p0 = tp * 4, q0 = tq * 4;
            float acc[4][4];
            #pragma unroll
            for (int a = 0; a < 4; a++)
                #pragma unroll
                for (int bb = 0; bb < 4; bb++) acc[a][bb] = 0.f;
            for (int h = 0; h < 128; h++) {
                float4 gp = *(const float4*)(Gs + h * GS_STRIDE + p0);
                float4 gq = *(const float4*)(Gs + h * GS_STRIDE + q0);
                acc[0][0] += gp.x * gq.x; acc[0][1] += gp.x * gq.y; acc[0][2] += gp.x * gq.z; acc[0][3] += gp.x * gq.w;
                acc[1][0] += gp.y * gq.x; acc[1][1] += gp.y * gq.y; acc[1][2] += gp.y * gq.z; acc[1][3] += gp.y * gq.w;
                acc[2][0] += gp.z * gq.x; acc[2][1] += gp.z * gq.y; acc[2][2] += gp.z * gq.z; acc[2][3] += gp.z * gq.w;
                acc[3][0] += gp.w * gq.x; acc[3][1] += gp.w * gq.y; acc[3][2] += gp.w * gq.z; acc[3][3] += gp.w * gq.w;
            }
            #pragma unroll
            for (int a = 0; a < 4; a++)
                #pragma unroll
                for (int bb = 0; bb < 4; bb++)
                    Ms[(p0 + a) * MS_STRIDE + (q0 + bb)] =
                        EPSP * acc[a][bb] + ((p0 + a) == (q0 + bb) ? 1.f : 0.f);
        }
        // ---- w = G^T s ----
        if (tid < 64) {
            float acc = 0.f;
            for (int h = 0; h < 128; h++) acc += Gs[h * GS_STRIDE + tid] * s_s[h];
            wv[tid] = acc;
        }
        __syncthreads();

        // ---- LDL^T with fused forward solve (augmented rhs) ----
        // Ln[j][k] = L[j][k] stored in natural row-major orientation.
        for (int k = 0; k < 64; k++) {
            float invd = 1.0f / Ms[k * MS_STRIDE + k];
            if (tid == 0) dinv[k] = invd;
            int j = k + 1 + (tid & 63);
            int part = tid >> 6;
            if (j < 64) {
                float lv = Ms[j * MS_STRIDE + k] * invd;
                if (part == 0) { Ln[j * MS_STRIDE + k] = lv; wv[j] -= lv * wv[k]; }
                for (int i = k + 1 + part; i < 64; i += 4)
                    Ms[j * MS_STRIDE + i] -= lv * Ms[k * MS_STRIDE + i];
            }
            __syncthreads();
        }

        // ---- diagonal scale + back solve L^T x = y ----
        if (tid < 64) wv[tid] *= dinv[tid];
        __syncthreads();
        for (int k = 63; k > 0; k--) {
            float xk = wv[k];
            // x[i] -= L[k][i] * x[k] for i < k ; L[k][i] = Ln[k][i] (row k, col i, i<k)
            if (tid < k) wv[tid] -= Ln[k * MS_STRIDE + tid] * xk;
            __syncthreads();
        }

        // ---- epilogue: c = s - eps*G*x ; h = o*tanh(c) ----
        if (tid < 128) {
            float acc = 0.f;
            for (int e = 0; e < 64; e++) acc += Gs[tid * GS_STRIDE + e] * wv[e];
            float cn = s_s[tid] - EPSP * acc;
            c_sm[tid] = cn;
            h_sm[tid] = o_s[tid] * tanhf(cn);
        }
        __syncthreads();
    }

    // ---- final linear ----
    if (tid < ODIM) {
        float acc = lin_b[tid];
        for (int k = 0; k < 128; k++) acc += h_sm[k] * lin_w[tid * 128 + k];
        out[b * ODIM + tid] = acc;
    }
}

extern "C" void kernel_launch(void* const* d_in, const int* in_sizes, int n_in,
                              void* d_out, int out_size) {
    const float* inputs  = (const float*)d_in[0];
    // d_in[1] = r (unused in ProxLSTM mode)
    const float* conv_w  = (const float*)d_in[2];
    const float* conv_b  = (const float*)d_in[3];
    const float* bn_g    = (const float*)d_in[4];
    const float* bn_b    = (const float*)d_in[5];
    const float* w_ih    = (const float*)d_in[6];
    const float* w_hh    = (const float*)d_in[7];
    const float* b_ih    = (const float*)d_in[8];
    const float* b_hh    = (const float*)d_in[9];
    const float* lin_w   = (const float*)d_in[10];
    const float* lin_b   = (const float*)d_in[11];
    float* out = (float*)d_out;

    cudaFuncSetAttribute(k4_scan, cudaFuncAttributeMaxDynamicSharedMemorySize, 73728);

    k0_prep<<<483, 256>>>(w_ih, w_hh, b_ih, b_hh, conv_w);
    k1_conv<<<1024, 256>>>(inputs, conv_b);
    k2a_stats<<<256, 256>>>();
    k2b_finalize<<<1, 64>>>(bn_g, bn_b);
    k3_zx<<<2048, 256>>>();
    k4_scan<<<64, 256, 73728>>>(lin_w, lin_b, w_ih, out);
}

// round 5
// speedup vs baseline: 1.0013x; 1.0013x over previous
#include <cuda_runtime.h>
#include <cuda_bf16.h>
#include <cstdint>
#include <math.h>

#define BDIM 64
#define TDIM 768
#define DDIM 128
#define EDIM 64
#define HDIM 128
#define ODIM 10
#define TC   256
#define G4   512
#define EPSP 5.0f

// ---------------- device scratch (no allocation allowed) ----------------
__device__ __align__(16) float g_emb[BDIM * TC * EDIM];     // conv output pre-BN [row][e]
__device__ __align__(16) float g_zx[(size_t)BDIM * TC * G4];// x-part gate preacts [row][512]
__device__ __align__(16) float g_whhT[HDIM * G4];           // [h][j]
__device__ __align__(16) float g_wihT[EDIM * G4];           // [e][j]
__device__ __align__(16) float g_convW[384 * EDIM];         // [(k*128+d)][e]
__device__ __align__(16) float g_bias[G4];                  // b_ih + b_hh
__device__ float g_part_s[256 * EDIM];
__device__ float g_part_ss[256 * EDIM];
__device__ float g_scale[EDIM];
__device__ float g_shift[EDIM];

__device__ __forceinline__ float sigf(float x) {
    return 1.0f / (1.0f + expf(-x));
}

// ---------------- K0: weight transposes + fused bias ----------------
__global__ __launch_bounds__(256) void k0_prep(
    const float* __restrict__ wih, const float* __restrict__ whh,
    const float* __restrict__ bih, const float* __restrict__ bhh,
    const float* __restrict__ conv_w) {
    int i = blockIdx.x * 256 + threadIdx.x;
    if (i < 65536) {                      // whhT[h][j] = whh[j][h]
        int h = i >> 9, j = i & 511;
        g_whhT[i] = whh[j * HDIM + h];
    } else if (i < 65536 + 32768) {       // wihT[e][j] = wih[j][e]
        int m = i - 65536;
        int e = m >> 9, j = m & 511;
        g_wihT[m] = wih[j * EDIM + e];
    } else if (i < 65536 + 32768 + 24576) { // convW[(k*128+d)][e] = conv_w[e][d][k]
        int m = i - 65536 - 32768;
        int q = m >> 6, e = m & 63;
        int k = q >> 7, d = q & 127;
        g_convW[m] = conv_w[e * 384 + d * 3 + k];
    } else if (i < 65536 + 32768 + 24576 + 512) {
        int j = i - 65536 - 32768 - 24576;
        g_bias[j] = bih[j] + bhh[j];
    }
}

// ---------------- K1: L2-normalize + Conv1d (non-overlapping => GEMM) ----------------
// grid = 64 b * 16 segs; block handles 16 conv rows (48 input rows)
__global__ __launch_bounds__(256) void k1_conv(
    const float* __restrict__ in, const float* __restrict__ conv_b) {
    __shared__ float xn[48 * 128];
    __shared__ float invn[48];
    int tid = threadIdx.x;
    int b = blockIdx.x >> 4, seg = blockIdx.x & 15;

    const float4* src = (const float4*)(in + ((size_t)b * TDIM + seg * 48) * DDIM);
    float4* d4 = (float4*)xn;
    for (int i = tid; i < 1536; i += 256) d4[i] = src[i];
    __syncthreads();

    int warp = tid >> 5, lane = tid & 31;
    for (int r = warp; r < 48; r += 8) {
        float v = 0.f;
        #pragma unroll
        for (int q = 0; q < 4; q++) { float x = xn[r * 128 + lane + q * 32]; v += x * x; }
        #pragma unroll
        for (int off = 16; off; off >>= 1) v += __shfl_down_sync(0xffffffffu, v, off);
        if (lane == 0) invn[r] = 1.0f / fmaxf(sqrtf(v), 1e-12f);
    }
    __syncthreads();
    for (int i = tid; i < 6144; i += 256) xn[i] *= invn[i >> 7];
    __syncthreads();

    // GEMM: 16 conv rows x 64 cols, contraction over 384
    int e = tid & 63, rg = tid >> 6;  // 4 row-groups of 4 rows
    float acc0 = 0.f, acc1 = 0.f, acc2 = 0.f, acc3 = 0.f;
    const float* xr = xn + rg * 4 * 384;
    for (int q = 0; q < 384; q++) {
        float wv = g_convW[q * 64 + e];
        acc0 += xr[q] * wv;
        acc1 += xr[q + 384] * wv;
        acc2 += xr[q + 768] * wv;
        acc3 += xr[q + 1152] * wv;
    }
    float cb = conv_b[e];
    int row0 = b * TC + seg * 16 + rg * 4;
    g_emb[(row0 + 0) * 64 + e] = acc0 + cb;
    g_emb[(row0 + 1) * 64 + e] = acc1 + cb;
    g_emb[(row0 + 2) * 64 + e] = acc2 + cb;
    g_emb[(row0 + 3) * 64 + e] = acc3 + cb;
}

// ---------------- K2a: BN partial sums (deterministic, no atomics) ----------------
__global__ __launch_bounds__(256) void k2a_stats() {
    __shared__ float ps[256], pss[256];
    int tid = threadIdx.x;
    int r0 = blockIdx.x * 64;
    int e = tid & 63, qr = tid >> 6;
    float s = 0.f, ss = 0.f;
    for (int u = 0; u < 16; u++) {
        float v = g_emb[(r0 + qr * 16 + u) * 64 + e];
        s += v; ss += v * v;
    }
    ps[tid] = s; pss[tid] = ss;
    __syncthreads();
    if (tid < 64) {
        s  = ps[tid]  + ps[tid + 64]  + ps[tid + 128]  + ps[tid + 192];
        ss = pss[tid] + pss[tid + 64] + pss[tid + 128] + pss[tid + 192];
        g_part_s[blockIdx.x * 64 + tid] = s;
        g_part_ss[blockIdx.x * 64 + tid] = ss;
    }
}

// ---------------- K2b: finalize BN scale/shift ----------------
__global__ __launch_bounds__(64) void k2b_finalize(
    const float* __restrict__ gamma, const float* __restrict__ beta) {
    int e = threadIdx.x;
    float s = 0.f, ss = 0.f;
    for (int blk = 0; blk < 256; blk++) {
        s  += g_part_s[blk * 64 + e];
        ss += g_part_ss[blk * 64 + e];
    }
    const float inv_n = 1.0f / 16384.0f;
    float mean = s * inv_n;
    float var = ss * inv_n - mean * mean;
    float sc = gamma[e] * rsqrtf(var + 1e-5f);
    g_scale[e] = sc;
    g_shift[e] = beta[e] - mean * sc;
}

// ---------------- K3: zx = ReLU(BN(emb)) @ wihT + bias ----------------
// grid 2048, each block 8 rows x 512 cols
__global__ __launch_bounds__(256) void k3_zx() {
    __shared__ float act[512];
    int tid = threadIdx.x;
    int r0 = blockIdx.x * 8;
    for (int i = tid; i < 512; i += 256) {
        int rr = i >> 6, e = i & 63;
        float a = g_emb[(r0 + rr) * 64 + e];
        act[i] = fmaxf(a * g_scale[e] + g_shift[e], 0.f);
    }
    __syncthreads();
    int j0 = tid, j1 = tid + 256;
    float acc0[8], acc1[8];
    float b0 = g_bias[j0], b1 = g_bias[j1];
    #pragma unroll
    for (int u = 0; u < 8; u++) { acc0[u] = b0; acc1[u] = b1; }
    for (int e = 0; e < 64; e++) {
        float w0 = g_wihT[e * 512 + j0];
        float w1 = g_wihT[e * 512 + j1];
        #pragma unroll
        for (int u = 0; u < 8; u++) {
            float a = act[u * 64 + e];
            acc0[u] += a * w0;
            acc1[u] += a * w1;
        }
    }
    #pragma unroll
    for (int u = 0; u < 8; u++) {
        float* zr = g_zx + ((size_t)(r0 + u)) * 512;
        zr[j0] = acc0[u];
        zr[j1] = acc1[u];
    }
}

// ---------------- K4: recurrent scan (one block per batch row) ----------------
// Woodbury: c = s - eps*G*(I + eps*G^T G)^{-1} G^T s,  G: [128][64]
#define GS_STRIDE 68
#define MS_STRIDE 65
__global__ __launch_bounds__(256) void k4_scan(
    const float* __restrict__ lin_w, const float* __restrict__ lin_b,
    const float* __restrict__ wih, float* __restrict__ out) {
    extern __shared__ float sm[];
    float* Gs  = sm;                 // 128*68 = 8704
    float* Ms  = sm + 8704;          // 64*65  = 4160
    float* Ln  = sm + 12864;         // 64*65  = 4160  (L natural: Ln[j][k] = L[j][k], j>k)
    float* i_s = sm + 17024;
    float* f_s = sm + 17152;
    float* gg_s= sm + 17280;
    float* o_s = sm + 17408;
    float* s_s = sm + 17536;
    float* ai  = sm + 17664;
    float* af  = sm + 17792;
    float* ag  = sm + 17920;
    float* h_sm= sm + 18048;
    float* c_sm= sm + 18176;
    float* wv  = sm + 18304;
    float* dinv= sm + 18368;         // end 18432 floats = 73728 B

    int tid = threadIdx.x;
    int b = blockIdx.x;

    if (tid < 128) { h_sm[tid] = 0.f; c_sm[tid] = 0.f; }
    __syncthreads();

    for (int t = 0; t < TC; t++) {
        // ---- z = zx + h @ whhT ; gates ----
        {
            const float* zrow = g_zx + ((size_t)(b * TC + t)) * 512;
            float a0 = zrow[tid], a1 = zrow[tid + 256];
            #pragma unroll 4
            for (int hh = 0; hh < 128; hh += 4) {
                float h0 = h_sm[hh], h1 = h_sm[hh + 1], h2 = h_sm[hh + 2], h3 = h_sm[hh + 3];
                const float* wp = g_whhT + hh * 512 + tid;
                a0 += h0 * wp[0];    a1 += h0 * wp[256];
                a0 += h1 * wp[512];  a1 += h1 * wp[768];
                a0 += h2 * wp[1024]; a1 += h2 * wp[1280];
                a0 += h3 * wp[1536]; a1 += h3 * wp[1792];
            }
            if (tid < 128) { i_s[tid] = sigf(a0); gg_s[tid] = tanhf(a1); }
            else           { f_s[tid - 128] = sigf(a0); o_s[tid - 128] = sigf(a1); }
        }
        __syncthreads();

        // ---- s and Jacobian row coefficients ----
        if (tid < 128) {
            float iv = i_s[tid], fv = f_s[tid], gv = gg_s[tid], cv = c_sm[tid];
            s_s[tid] = fv * cv + iv * gv;
            ai[tid] = iv * (1.f - iv) * gv;
            af[tid] = fv * (1.f - fv) * cv;
            ag[tid] = iv * (1.f - gv * gv);
        }
        __syncthreads();

        // ---- G[h][e] = ai*Wi + af*Wf + ag*Wg ----
        {
            int e = tid & 63, hg = tid >> 6;
            #pragma unroll 4
            for (int u = 0; u < 32; u++) {
                int h = hg * 32 + u;
                float g = ai[h] * wih[h * 64 + e]
                        + af[h] * wih[(128 + h) * 64 + e]
                        + ag[h] * wih[(256 + h) * 64 + e];
                Gs[h * GS_STRIDE + e] = g;
            }
        }
        __syncthreads();

        // ---- M = I + eps*G^T G (4x4 register tiles) ----
        {
            int tp = tid >> 4, tq = tid & 15;
            int p0 = tp * 4, q0 = tq * 4;
            float acc[4][4];
            #pragma unroll
            for (int a = 0; a < 4; a++)
                #pragma unroll
                for (int bb = 0; bb < 4; bb++) acc[a][bb] = 0.f;
            for (int h = 0; h < 128; h++) {
                float4 gp = *(const float4*)(Gs + h * GS_STRIDE + p0);
                float4 gq = *(const float4*)(Gs + h * GS_STRIDE + q0);
                acc[0][0] += gp.x * gq.x; acc[0][1] += gp.x * gq.y; acc[0][2] += gp.x * gq.z; acc[0][3] += gp.x * gq.w;
                acc[1][0] += gp.y * gq.x; acc[1][1] += gp.y * gq.y; acc[1][2] += gp.y * gq.z; acc[1][3] += gp.y * gq.w;
                acc[2][0] += gp.z * gq.x; acc[2][1] += gp.z * gq.y; acc[2][2] += gp.z * gq.z; acc[2][3] += gp.z * gq.w;
                acc[3][0] += gp.w * gq.x; acc[3][1] += gp.w * gq.y; acc[3][2] += gp.w * gq.z; acc[3][3] += gp.w * gq.w;
            }
            #pragma unroll
            for (int a = 0; a < 4; a++)
                #pragma unroll
                for (int bb = 0; bb < 4; bb++)
                    Ms[(p0 + a) * MS_STRIDE + (q0 + bb)] =
                        EPSP * acc[a][bb] + ((p0 + a) == (q0 + bb) ? 1.f : 0.f);
        }
        // ---- w = G^T s ----
        if (tid < 64) {
            float acc = 0.f;
            for (int h = 0; h < 128; h++) acc += Gs[h * GS_STRIDE + tid] * s_s[h];
            wv[tid] = acc;
        }
        __syncthreads();

        // ---- LDL^T with fused forward solve (augmented rhs) ----
        // Ln[j][k] = L[j][k] stored in natural row-major orientation.
        for (int k = 0; k < 64; k++) {
            float invd = 1.0f / Ms[k * MS_STRIDE + k];
            if (tid == 0) dinv[k] = invd;
            int j = k + 1 + (tid & 63);
            int part = tid >> 6;
            if (j < 64) {
                float lv = Ms[j * MS_STRIDE + k] * invd;
                if (part == 0) { Ln[j * MS_STRIDE + k] = lv; wv[j] -= lv * wv[k]; }
                for (int i = k + 1 + part; i < 64; i += 4)
                    Ms[j * MS_STRIDE + i] -= lv * Ms[k * MS_STRIDE + i];
            }
            __syncthreads();
        }

        // ---- diagonal scale + back solve L^T x = y ----
        if (tid < 64) wv[tid] *= dinv[tid];
        __syncthreads();
        for (int k = 63; k > 0; k--) {
            float xk = wv[k];
            // x[i] -= L[k][i] * x[k] for i < k ; L[k][i] = Ln[k][i] (row k, col i, i<k)
            if (tid < k) wv[tid] -= Ln[k * MS_STRIDE + tid] * xk;
            __syncthreads();
        }

        // ---- epilogue: c = s - eps*G*x ; h = o*tanh(c) ----
        if (tid < 128) {
            float acc = 0.f;
            for (int e = 0; e < 64; e++) acc += Gs[tid * GS_STRIDE + e] * wv[e];
            float cn = s_s[tid] - EPSP * acc;
            c_sm[tid] = cn;
            h_sm[tid] = o_s[tid] * tanhf(cn);
        }
        __syncthreads();
    }

    // ---- final linear ----
    if (tid < ODIM) {
        float acc = lin_b[tid];
        for (int k = 0; k < 128; k++) acc += h_sm[k] * lin_w[tid * 128 + k];
        out[b * ODIM + tid] = acc;
    }
}

extern "C" void kernel_launch(void* const* d_in, const int* in_sizes, int n_in,
                              void* d_out, int out_size) {
    const float* inputs  = (const float*)d_in[0];
    // d_in[1] = r (unused in ProxLSTM mode)
    const float* conv_w  = (const float*)d_in[2];
    const float* conv_b  = (const float*)d_in[3];
    const float* bn_g    = (const float*)d_in[4];
    const float* bn_b    = (const float*)d_in[5];
    const float* w_ih    = (const float*)d_in[6];
    const float* w_hh    = (const float*)d_in[7];
    const float* b_ih    = (const float*)d_in[8];
    const float* b_hh    = (const float*)d_in[9];
    const float* lin_w   = (const float*)d_in[10];
    const float* lin_b   = (const float*)d_in[11];
    float* out = (float*)d_out;

    cudaFuncSetAttribute(k4_scan, cudaFuncAttributeMaxDynamicSharedMemorySize, 73728);

    k0_prep<<<483, 256>>>(w_ih, w_hh, b_ih, b_hh, conv_w);
    k1_conv<<<1024, 256>>>(inputs, conv_b);
    k2a_stats<<<256, 256>>>();
    k2b_finalize<<<1, 64>>>(bn_g, bn_b);
    k3_zx<<<2048, 256>>>();
    k4_scan<<<64, 256, 73728>>>(lin_w, lin_b, w_ih, out);
}

// round 8
// speedup vs baseline: 1.0293x; 1.0280x over previous
#include <cuda_runtime.h>
#include <cuda_bf16.h>
#include <cstdint>
#include <math.h>

#define BDIM 64
#define TDIM 768
#define DDIM 128
#define EDIM 64
#define HDIM 128
#define ODIM 10
#define TC   256
#define G4   512
#define EPSP 5.0f
#define FULLM 0xffffffffu

// ---------------- device scratch (no allocation allowed) ----------------
__device__ __align__(16) float g_emb[BDIM * TC * EDIM];
__device__ __align__(16) float g_zx[(size_t)BDIM * TC * G4];
__device__ __align__(16) float g_whhT[HDIM * G4];
__device__ __align__(16) float g_wihT[EDIM * G4];
__device__ __align__(16) float g_convW[384 * EDIM];
__device__ __align__(16) float g_bias[G4];
__device__ float g_part_s[256 * EDIM];
__device__ float g_part_ss[256 * EDIM];
__device__ float g_scale[EDIM];
__device__ float g_shift[EDIM];

__device__ __forceinline__ float sigf(float x) { return 1.0f / (1.0f + expf(-x)); }

// ---------------- K0 ----------------
__global__ __launch_bounds__(256) void k0_prep(
    const float* __restrict__ wih, const float* __restrict__ whh,
    const float* __restrict__ bih, const float* __restrict__ bhh,
    const float* __restrict__ conv_w) {
    int i = blockIdx.x * 256 + threadIdx.x;
    if (i < 65536) {
        int h = i >> 9, j = i & 511;
        g_whhT[i] = whh[j * HDIM + h];
    } else if (i < 65536 + 32768) {
        int m = i - 65536;
        int e = m >> 9, j = m & 511;
        g_wihT[m] = wih[j * EDIM + e];
    } else if (i < 65536 + 32768 + 24576) {
        int m = i - 65536 - 32768;
        int q = m >> 6, e = m & 63;
        int k = q >> 7, d = q & 127;
        g_convW[m] = conv_w[e * 384 + d * 3 + k];
    } else if (i < 65536 + 32768 + 24576 + 512) {
        int j = i - 65536 - 32768 - 24576;
        g_bias[j] = bih[j] + bhh[j];
    }
}

// ---------------- K1: L2-normalize + conv-as-GEMM ----------------
__global__ __launch_bounds__(256) void k1_conv(
    const float* __restrict__ in, const float* __restrict__ conv_b) {
    __shared__ float xn[48 * 128];
    __shared__ float invn[48];
    int tid = threadIdx.x;
    int b = blockIdx.x >> 4, seg = blockIdx.x & 15;

    const float4* src = (const float4*)(in + ((size_t)b * TDIM + seg * 48) * DDIM);
    float4* d4 = (float4*)xn;
    for (int i = tid; i < 1536; i += 256) d4[i] = src[i];
    __syncthreads();

    int warp = tid >> 5, lane = tid & 31;
    for (int r = warp; r < 48; r += 8) {
        float v = 0.f;
        #pragma unroll
        for (int q = 0; q < 4; q++) { float x = xn[r * 128 + lane + q * 32]; v += x * x; }
        #pragma unroll
        for (int off = 16; off; off >>= 1) v += __shfl_down_sync(FULLM, v, off);
        if (lane == 0) invn[r] = 1.0f / fmaxf(sqrtf(v), 1e-12f);
    }
    __syncthreads();
    for (int i = tid; i < 6144; i += 256) xn[i] *= invn[i >> 7];
    __syncthreads();

    int e = tid & 63, rg = tid >> 6;
    float acc0 = 0.f, acc1 = 0.f, acc2 = 0.f, acc3 = 0.f;
    const float* xr = xn + rg * 4 * 384;
    for (int q = 0; q < 384; q++) {
        float wv = g_convW[q * 64 + e];
        acc0 += xr[q] * wv;
        acc1 += xr[q + 384] * wv;
        acc2 += xr[q + 768] * wv;
        acc3 += xr[q + 1152] * wv;
    }
    float cb = conv_b[e];
    int row0 = b * TC + seg * 16 + rg * 4;
    g_emb[(row0 + 0) * 64 + e] = acc0 + cb;
    g_emb[(row0 + 1) * 64 + e] = acc1 + cb;
    g_emb[(row0 + 2) * 64 + e] = acc2 + cb;
    g_emb[(row0 + 3) * 64 + e] = acc3 + cb;
}

// ---------------- K2a/K2b: deterministic BN stats ----------------
__global__ __launch_bounds__(256) void k2a_stats() {
    __shared__ float ps[256], pss[256];
    int tid = threadIdx.x;
    int r0 = blockIdx.x * 64;
    int e = tid & 63, qr = tid >> 6;
    float s = 0.f, ss = 0.f;
    for (int u = 0; u < 16; u++) {
        float v = g_emb[(r0 + qr * 16 + u) * 64 + e];
        s += v; ss += v * v;
    }
    ps[tid] = s; pss[tid] = ss;
    __syncthreads();
    if (tid < 64) {
        s  = ps[tid]  + ps[tid + 64]  + ps[tid + 128]  + ps[tid + 192];
        ss = pss[tid] + pss[tid + 64] + pss[tid + 128] + pss[tid + 192];
        g_part_s[blockIdx.x * 64 + tid] = s;
        g_part_ss[blockIdx.x * 64 + tid] = ss;
    }
}

__global__ __launch_bounds__(64) void k2b_finalize(
    const float* __restrict__ gamma, const float* __restrict__ beta) {
    int e = threadIdx.x;
    float s = 0.f, ss = 0.f;
    for (int blk = 0; blk < 256; blk++) {
        s  += g_part_s[blk * 64 + e];
        ss += g_part_ss[blk * 64 + e];
    }
    const float inv_n = 1.0f / 16384.0f;
    float mean = s * inv_n;
    float var = ss * inv_n - mean * mean;
    float sc = gamma[e] * rsqrtf(var + 1e-5f);
    g_scale[e] = sc;
    g_shift[e] = beta[e] - mean * sc;
}

// ---------------- K3: zx = ReLU(BN(emb)) @ wihT + bias ----------------
__global__ __launch_bounds__(256) void k3_zx() {
    __shared__ float act[512];
    int tid = threadIdx.x;
    int r0 = blockIdx.x * 8;
    for (int i = tid; i < 512; i += 256) {
        int rr = i >> 6, e = i & 63;
        float a = g_emb[(r0 + rr) * 64 + e];
        act[i] = fmaxf(a * g_scale[e] + g_shift[e], 0.f);
    }
    __syncthreads();
    int j0 = tid, j1 = tid + 256;
    float acc0[8], acc1[8];
    float b0 = g_bias[j0], b1 = g_bias[j1];
    #pragma unroll
    for (int u = 0; u < 8; u++) { acc0[u] = b0; acc1[u] = b1; }
    for (int e = 0; e < 64; e++) {
        float w0 = g_wihT[e * 512 + j0];
        float w1 = g_wihT[e * 512 + j1];
        #pragma unroll
        for (int u = 0; u < 8; u++) {
            float a = act[u * 64 + e];
            acc0[u] += a * w0;
            acc1[u] += a * w1;
        }
    }
    #pragma unroll
    for (int u = 0; u < 8; u++) {
        float* zr = g_zx + ((size_t)(r0 + u)) * 512;
        zr[j0] = acc0[u];
        zr[j1] = acc1[u];
    }
}

// ---------------- K4: recurrent scan, panel-blocked LDL^T ----------------
#define GS_STRIDE 68
#define MS_STRIDE 65
__global__ __launch_bounds__(256) void k4_scan(
    const float* __restrict__ lin_w, const float* __restrict__ lin_b,
    const float* __restrict__ wih, float* __restrict__ out) {
    extern __shared__ float sm[];
    float* Gs  = sm;                 // 128*68 = 8704
    float* Ms  = sm + 8704;          // 64*65
    float* Ln  = sm + 12864;         // 64*65 natural: Ln[j][k] = L[j][k]
    float* i_s = sm + 17024;
    float* f_s = sm + 17152;
    float* gg_s= sm + 17280;
    float* o_s = sm + 17408;
    float* s_s = sm + 17536;
    float* ai  = sm + 17664;
    float* af  = sm + 17792;
    float* ag  = sm + 17920;
    float* h_sm= sm + 18048;
    float* c_sm= sm + 18176;
    float* wv  = sm + 18304;
    float* dinv= sm + 18368;         // end 18432 floats

    int tid = threadIdx.x;
    int b = blockIdx.x;
    int warp = tid >> 5, lane = tid & 31;

    if (tid < 128) { h_sm[tid] = 0.f; c_sm[tid] = 0.f; }
    __syncthreads();

    for (int t = 0; t < TC; t++) {
        // ---- phase 1: z = zx + h @ whhT ; gates ----
        {
            const float* zrow = g_zx + ((size_t)(b * TC + t)) * 512;
            float a0 = zrow[tid], a1 = zrow[tid + 256];
            #pragma unroll 4
            for (int hh = 0; hh < 128; hh += 4) {
                float h0 = h_sm[hh], h1 = h_sm[hh + 1], h2 = h_sm[hh + 2], h3 = h_sm[hh + 3];
                const float* wp = g_whhT + hh * 512 + tid;
                a0 += h0 * wp[0];    a1 += h0 * wp[256];
                a0 += h1 * wp[512];  a1 += h1 * wp[768];
                a0 += h2 * wp[1024]; a1 += h2 * wp[1280];
                a0 += h3 * wp[1536]; a1 += h3 * wp[1792];
            }
            if (tid < 128) { i_s[tid] = sigf(a0); gg_s[tid] = tanhf(a1); }
            else           { f_s[tid - 128] = sigf(a0); o_s[tid - 128] = sigf(a1); }
        }
        __syncthreads();

        // ---- phase 2: s and Jacobian coefficients ----
        if (tid < 128) {
            float iv = i_s[tid], fv = f_s[tid], gv = gg_s[tid], cv = c_sm[tid];
            s_s[tid] = fv * cv + iv * gv;
            ai[tid] = iv * (1.f - iv) * gv;
            af[tid] = fv * (1.f - fv) * cv;
            ag[tid] = iv * (1.f - gv * gv);
        }
        __syncthreads();

        // ---- phase 3: G[h][e] ----
        {
            int e = tid & 63, hg = tid >> 6;
            #pragma unroll 4
            for (int u = 0; u < 32; u++) {
                int h = hg * 32 + u;
                float g = ai[h] * wih[h * 64 + e]
                        + af[h] * wih[(128 + h) * 64 + e]
                        + ag[h] * wih[(256 + h) * 64 + e];
                Gs[h * GS_STRIDE + e] = g;
            }
        }
        __syncthreads();

        // ---- phase 4: M = I + eps*G^T G ; w = G^T s ----
        {
            int tp = tid >> 4, tq = tid & 15;
            int p0 = tp * 4, q0 = tq * 4;
            float acc[4][4];
            #pragma unroll
            for (int a = 0; a < 4; a++)
                #pragma unroll
                for (int bb = 0; bb < 4; bb++) acc[a][bb] = 0.f;
            for (int h = 0; h < 128; h++) {
                float4 gp = *(const float4*)(Gs + h * GS_STRIDE + p0);
                float4 gq = *(const float4*)(Gs + h * GS_STRIDE + q0);
                acc[0][0] += gp.x * gq.x; acc[0][1] += gp.x * gq.y; acc[0][2] += gp.x * gq.z; acc[0][3] += gp.x * gq.w;
                acc[1][0] += gp.y * gq.x; acc[1][1] += gp.y * gq.y; acc[1][2] += gp.y * gq.z; acc[1][3] += gp.y * gq.w;
                acc[2][0] += gp.z * gq.x; acc[2][1] += gp.z * gq.y; acc[2][2] += gp.z * gq.z; acc[2][3] += gp.z * gq.w;
                acc[3][0] += gp.w * gq.x; acc[3][1] += gp.w * gq.y; acc[3][2] += gp.w * gq.z; acc[3][3] += gp.w * gq.w;
            }
            #pragma unroll
            for (int a = 0; a < 4; a++)
                #pragma unroll
                for (int bb = 0; bb < 4; bb++)
                    Ms[(p0 + a) * MS_STRIDE + (q0 + bb)] =
                        EPSP * acc[a][bb] + ((p0 + a) == (q0 + bb) ? 1.f : 0.f);
        }
        if (tid < 64) {
            float acc = 0.f;
            for (int h = 0; h < 128; h++) acc += Gs[h * GS_STRIDE + tid] * s_s[h];
            wv[tid] = acc;
        }
        __syncthreads();

        // ---- panel-blocked LDL^T (8 panels of 8 cols) ----
        #pragma unroll 1
        for (int pp = 0; pp < 8; pp++) {
            int p0 = pp * 8;
            // phase A: warp 0 factors the 64x8 panel + forward solve
            if (warp == 0) {
                int j0 = p0 + lane;
                int j1 = p0 + 32 + lane;
                #pragma unroll 1
                for (int kl = 0; kl < 8; kl++) {
                    int k = p0 + kl;
                    float invd = __fdividef(1.0f, Ms[k * MS_STRIDE + k]);
                    if (lane == 0) dinv[k] = invd;
                    if (j0 > k && j0 < 64) {
                        float lv = Ms[j0 * MS_STRIDE + k] * invd;
                        Ln[j0 * MS_STRIDE + k] = lv;
                        wv[j0] -= lv * wv[k];
                        for (int c = kl + 1; c < 8; c++)
                            Ms[j0 * MS_STRIDE + p0 + c] -= lv * Ms[k * MS_STRIDE + p0 + c];
                    }
                    if (j1 < 64) {
                        float lv = Ms[j1 * MS_STRIDE + k] * invd;
                        Ln[j1 * MS_STRIDE + k] = lv;
                        wv[j1] -= lv * wv[k];
                        for (int c = kl + 1; c < 8; c++)
                            Ms[j1 * MS_STRIDE + p0 + c] -= lv * Ms[k * MS_STRIDE + p0 + c];
                    }
                    __syncwarp();
                }
            }
            __syncthreads();
            // phase B: rank-8 trailing update on [r0..63]^2 (keeps full symmetry)
            int r0 = p0 + 8;
            int R = 64 - r0;
            if (R > 0) {
                for (int jq = warp; jq * 4 < R; jq += 8) {
                    int jb = r0 + jq * 4;
                    for (int i = r0 + lane; i < 64; i += 32) {
                        float a0 = Ms[i * MS_STRIDE + p0 + 0];
                        float a1 = Ms[i * MS_STRIDE + p0 + 1];
                        float a2 = Ms[i * MS_STRIDE + p0 + 2];
                        float a3 = Ms[i * MS_STRIDE + p0 + 3];
                        float a4 = Ms[i * MS_STRIDE + p0 + 4];
                        float a5 = Ms[i * MS_STRIDE + p0 + 5];
                        float a6 = Ms[i * MS_STRIDE + p0 + 6];
                        float a7 = Ms[i * MS_STRIDE + p0 + 7];
                        #pragma unroll
                        for (int u = 0; u < 4; u++) {
                            int j = jb + u;
                            const float* lr = Ln + j * MS_STRIDE + p0;
                            float acc = Ms[j * MS_STRIDE + i];
                            acc -= lr[0] * a0 + lr[1] * a1 + lr[2] * a2 + lr[3] * a3
                                 + lr[4] * a4 + lr[5] * a5 + lr[6] * a6 + lr[7] * a7;
                            Ms[j * MS_STRIDE + i] = acc;
                        }
                    }
                }
                __syncthreads();
            }
        }

        // ---- back solve (warp 0, register-resident, zero barriers) ----
        if (warp == 0) {
            float x0 = wv[lane] * dinv[lane];
            float x1 = wv[lane + 32] * dinv[lane + 32];
            #pragma unroll 1
            for (int k = 63; k >= 32; k--) {
                float xk = __shfl_sync(FULLM, x1, k - 32);
                if (lane + 32 < k) x1 -= Ln[k * MS_STRIDE + lane + 32] * xk;
                x0 -= Ln[k * MS_STRIDE + lane] * xk;
            }
            #pragma unroll 1
            for (int k = 31; k >= 1; k--) {
                float xk = __shfl_sync(FULLM, x0, k);
                if (lane < k) x0 -= Ln[k * MS_STRIDE + lane] * xk;
            }
            wv[lane] = x0;
            wv[lane + 32] = x1;
        }
        __syncthreads();

        // ---- epilogue: c = s - eps*G*x ; h = o*tanh(c) ----
        if (tid < 128) {
            float acc = 0.f;
            for (int e = 0; e < 64; e++) acc += Gs[tid * GS_STRIDE + e] * wv[e];
            float cn = s_s[tid] - EPSP * acc;
            c_sm[tid] = cn;
            h_sm[tid] = o_s[tid] * tanhf(cn);
        }
        __syncthreads();
    }

    // ---- final linear ----
    if (tid < ODIM) {
        float acc = lin_b[tid];
        for (int k = 0; k < 128; k++) acc += h_sm[k] * lin_w[tid * 128 + k];
        out[b * ODIM + tid] = acc;
    }
}

extern "C" void kernel_launch(void* const* d_in, const int* in_sizes, int n_in,
                              void* d_out, int out_size) {
    const float* inputs  = (const float*)d_in[0];
    const float* conv_w  = (const float*)d_in[2];
    const float* conv_b  = (const float*)d_in[3];
    const float* bn_g    = (const float*)d_in[4];
    const float* bn_b    = (const float*)d_in[5];
    const float* w_ih    = (const float*)d_in[6];
    const float* w_hh    = (const float*)d_in[7];
    const float* b_ih    = (const float*)d_in[8];
    const float* b_hh    = (const float*)d_in[9];
    const float* lin_w   = (const float*)d_in[10];
    const float* lin_b   = (const float*)d_in[11];
    float* out = (float*)d_out;

    cudaFuncSetAttribute(k4_scan, cudaFuncAttributeMaxDynamicSharedMemorySize, 73728);

    k0_prep<<<483, 256>>>(w_ih, w_hh, b_ih, b_hh, conv_w);
    k1_conv<<<1024, 256>>>(inputs, conv_b);
    k2a_stats<<<256, 256>>>();
    k2b_finalize<<<1, 64>>>(bn_g, bn_b);
    k3_zx<<<2048, 256>>>();
    k4_scan<<<64, 256, 73728>>>(lin_w, lin_b, w_ih, out);
}

// round 10
// speedup vs baseline: 1.1393x; 1.1069x over previous
#include <cuda_runtime.h>
#include <cuda_bf16.h>
#include <cstdint>
#include <math.h>

#define BDIM 64
#define TDIM 768
#define DDIM 128
#define EDIM 64
#define HDIM 128
#define ODIM 10
#define TC   256
#define G4   512
#define EPSP 5.0f
#define FULLM 0xffffffffu

// ---------------- device scratch (no allocation allowed) ----------------
__device__ __align__(16) float g_emb[BDIM * TC * EDIM];
__device__ __align__(16) float g_zx[(size_t)BDIM * TC * G4];
__device__ __align__(16) float g_whhT[HDIM * G4];
__device__ __align__(16) float g_wihT[EDIM * G4];
__device__ __align__(16) float g_convW[384 * EDIM];
__device__ __align__(16) float g_bias[G4];
__device__ float g_part_s[256 * EDIM];
__device__ float g_part_ss[256 * EDIM];
__device__ float g_scale[EDIM];
__device__ float g_shift[EDIM];

__device__ __forceinline__ float sigf(float x) { return 1.0f / (1.0f + expf(-x)); }

// ---------------- K0 ----------------
__global__ __launch_bounds__(256) void k0_prep(
    const float* __restrict__ wih, const float* __restrict__ whh,
    const float* __restrict__ bih, const float* __restrict__ bhh,
    const float* __restrict__ conv_w) {
    int i = blockIdx.x * 256 + threadIdx.x;
    if (i < 65536) {
        int h = i >> 9, j = i & 511;
        g_whhT[i] = whh[j * HDIM + h];
    } else if (i < 65536 + 32768) {
        int m = i - 65536;
        int e = m >> 9, j = m & 511;
        g_wihT[m] = wih[j * EDIM + e];
    } else if (i < 65536 + 32768 + 24576) {
        int m = i - 65536 - 32768;
        int q = m >> 6, e = m & 63;
        int k = q >> 7, d = q & 127;
        g_convW[m] = conv_w[e * 384 + d * 3 + k];
    } else if (i < 65536 + 32768 + 24576 + 512) {
        int j = i - 65536 - 32768 - 24576;
        g_bias[j] = bih[j] + bhh[j];
    }
}

// ---------------- K1: L2-normalize + conv-as-GEMM ----------------
__global__ __launch_bounds__(256) void k1_conv(
    const float* __restrict__ in, const float* __restrict__ conv_b) {
    __shared__ float xn[48 * 128];
    __shared__ float invn[48];
    int tid = threadIdx.x;
    int b = blockIdx.x >> 4, seg = blockIdx.x & 15;

    const float4* src = (const float4*)(in + ((size_t)b * TDIM + seg * 48) * DDIM);
    float4* d4 = (float4*)xn;
    for (int i = tid; i < 1536; i += 256) d4[i] = src[i];
    __syncthreads();

    int warp = tid >> 5, lane = tid & 31;
    for (int r = warp; r < 48; r += 8) {
        float v = 0.f;
        #pragma unroll
        for (int q = 0; q < 4; q++) { float x = xn[r * 128 + lane + q * 32]; v += x * x; }
        #pragma unroll
        for (int off = 16; off; off >>= 1) v += __shfl_down_sync(FULLM, v, off);
        if (lane == 0) invn[r] = 1.0f / fmaxf(sqrtf(v), 1e-12f);
    }
    __syncthreads();
    for (int i = tid; i < 6144; i += 256) xn[i] *= invn[i >> 7];
    __syncthreads();

    int e = tid & 63, rg = tid >> 6;
    float acc0 = 0.f, acc1 = 0.f, acc2 = 0.f, acc3 = 0.f;
    const float* xr = xn + rg * 4 * 384;
    for (int q = 0; q < 384; q++) {
        float wv = g_convW[q * 64 + e];
        acc0 += xr[q] * wv;
        acc1 += xr[q + 384] * wv;
        acc2 += xr[q + 768] * wv;
        acc3 += xr[q + 1152] * wv;
    }
    float cb = conv_b[e];
    int row0 = b * TC + seg * 16 + rg * 4;
    g_emb[(row0 + 0) * 64 + e] = acc0 + cb;
    g_emb[(row0 + 1) * 64 + e] = acc1 + cb;
    g_emb[(row0 + 2) * 64 + e] = acc2 + cb;
    g_emb[(row0 + 3) * 64 + e] = acc3 + cb;
}

// ---------------- K2a/K2b: deterministic BN stats ----------------
__global__ __launch_bounds__(256) void k2a_stats() {
    __shared__ float ps[256], pss[256];
    int tid = threadIdx.x;
    int r0 = blockIdx.x * 64;
    int e = tid & 63, qr = tid >> 6;
    float s = 0.f, ss = 0.f;
    for (int u = 0; u < 16; u++) {
        float v = g_emb[(r0 + qr * 16 + u) * 64 + e];
        s += v; ss += v * v;
    }
    ps[tid] = s; pss[tid] = ss;
    __syncthreads();
    if (tid < 64) {
        s  = ps[tid]  + ps[tid + 64]  + ps[tid + 128]  + ps[tid + 192];
        ss = pss[tid] + pss[tid + 64] + pss[tid + 128] + pss[tid + 192];
        g_part_s[blockIdx.x * 64 + tid] = s;
        g_part_ss[blockIdx.x * 64 + tid] = ss;
    }
}

__global__ __launch_bounds__(64) void k2b_finalize(
    const float* __restrict__ gamma, const float* __restrict__ beta) {
    int e = threadIdx.x;
    float s = 0.f, ss = 0.f;
    for (int blk = 0; blk < 256; blk++) {
        s  += g_part_s[blk * 64 + e];
        ss += g_part_ss[blk * 64 + e];
    }
    const float inv_n = 1.0f / 16384.0f;
    float mean = s * inv_n;
    float var = ss * inv_n - mean * mean;
    float sc = gamma[e] * rsqrtf(var + 1e-5f);
    g_scale[e] = sc;
    g_shift[e] = beta[e] - mean * sc;
}

// ---------------- K3: zx = ReLU(BN(emb)) @ wihT + bias ----------------
__global__ __launch_bounds__(256) void k3_zx() {
    __shared__ float act[512];
    int tid = threadIdx.x;
    int r0 = blockIdx.x * 8;
    for (int i = tid; i < 512; i += 256) {
        int rr = i >> 6, e = i & 63;
        float a = g_emb[(r0 + rr) * 64 + e];
        act[i] = fmaxf(a * g_scale[e] + g_shift[e], 0.f);
    }
    __syncthreads();
    int j0 = tid, j1 = tid + 256;
    float acc0[8], acc1[8];
    float b0 = g_bias[j0], b1 = g_bias[j1];
    #pragma unroll
    for (int u = 0; u < 8; u++) { acc0[u] = b0; acc1[u] = b1; }
    for (int e = 0; e < 64; e++) {
        float w0 = g_wihT[e * 512 + j0];
        float w1 = g_wihT[e * 512 + j1];
        #pragma unroll
        for (int u = 0; u < 8; u++) {
            float a = act[u * 64 + e];
            acc0[u] += a * w0;
            acc1[u] += a * w1;
        }
    }
    #pragma unroll
    for (int u = 0; u < 8; u++) {
        float* zr = g_zx + ((size_t)(r0 + u)) * 512;
        zr[j0] = acc0[u];
        zr[j1] = acc1[u];
    }
}

// ---------------- K4: recurrent scan ----------------
#define GS_STRIDE 68
#define MS_STRIDE 65
__global__ __launch_bounds__(256) void k4_scan(
    const float* __restrict__ lin_w, const float* __restrict__ lin_b,
    const float* __restrict__ wih, float* __restrict__ out) {
    extern __shared__ float sm[];
    float* Gs  = sm;                 // 128*68 = 8704
    float* Ms  = sm + 8704;          // 64*65
    float* Ln  = sm + 12864;         // 64*65
    float* i_s = sm + 17024;
    float* f_s = sm + 17152;
    float* gg_s= sm + 17280;
    float* o_s = sm + 17408;
    float* s_s = sm + 17536;
    float* ai  = sm + 17664;
    float* af  = sm + 17792;
    float* ag  = sm + 17920;
    float* h_sm= sm + 18048;
    float* c_sm= sm + 18176;
    float* wv  = sm + 18304;
    float* dinv= sm + 18368;         // end 18432 floats

    int tid = threadIdx.x;
    int b = blockIdx.x;
    int warp = tid >> 5, lane = tid & 31;

    // triangular tile map for the symmetric M-build: tid < 136 -> (tp_s, tq_s), tp_s <= tq_s
    int tp_s = 0, tq_s = 0; bool has_tile = false;
    {
        int idx = tid;
        #pragma unroll 1
        for (int p = 0; p < 16; p++) {
            int wdt = 16 - p;
            if (idx < wdt) { tp_s = p; tq_s = p + idx; has_tile = true; break; }
            idx -= wdt;
        }
    }

    if (tid < 128) { h_sm[tid] = 0.f; c_sm[tid] = 0.f; }
    __syncthreads();

    for (int t = 0; t < TC; t++) {
        // ---- phase 1: z = zx + h @ whhT (float2 vectorized) ; gates ----
        {
            const float* zrow = g_zx + ((size_t)(b * TC + t)) * 512;
            float2 zz = *(const float2*)(zrow + 2 * tid);
            float a0 = zz.x, a1 = zz.y;
            const float2* wbase = (const float2*)g_whhT + tid;  // row stride = 256 float2
            #pragma unroll 4
            for (int hh = 0; hh < 128; hh += 4) {
                float4 hv = *(const float4*)(h_sm + hh);
                float2 w0 = wbase[(hh + 0) * 256];
                float2 w1 = wbase[(hh + 1) * 256];
                float2 w2 = wbase[(hh + 2) * 256];
                float2 w3 = wbase[(hh + 3) * 256];
                a0 += hv.x * w0.x; a1 += hv.x * w0.y;
                a0 += hv.y * w1.x; a1 += hv.y * w1.y;
                a0 += hv.z * w2.x; a1 += hv.z * w2.y;
                a0 += hv.w * w3.x; a1 += hv.w * w3.y;
            }
            int gsel = tid >> 6, hh2 = (tid & 63) * 2;
            if (gsel == 0)      { i_s[hh2]  = sigf(a0);  i_s[hh2 + 1]  = sigf(a1); }
            else if (gsel == 1) { f_s[hh2]  = sigf(a0);  f_s[hh2 + 1]  = sigf(a1); }
            else if (gsel == 2) { gg_s[hh2] = tanhf(a0); gg_s[hh2 + 1] = tanhf(a1); }
            else                { o_s[hh2]  = sigf(a0);  o_s[hh2 + 1]  = sigf(a1); }
        }
        __syncthreads();

        // ---- phase 2: s and Jacobian coefficients ----
        if (tid < 128) {
            float iv = i_s[tid], fv = f_s[tid], gv = gg_s[tid], cv = c_sm[tid];
            s_s[tid] = fv * cv + iv * gv;
            ai[tid] = iv * (1.f - iv) * gv;
            af[tid] = fv * (1.f - fv) * cv;
            ag[tid] = iv * (1.f - gv * gv);
        }
        __syncthreads();

        // ---- phase 3: G[h][e] ----
        {
            int e = tid & 63, hg = tid >> 6;
            #pragma unroll 4
            for (int u = 0; u < 32; u++) {
                int h = hg * 32 + u;
                float g = ai[h] * wih[h * 64 + e]
                        + af[h] * wih[(128 + h) * 64 + e]
                        + ag[h] * wih[(256 + h) * 64 + e];
                Gs[h * GS_STRIDE + e] = g;
            }
        }
        __syncthreads();

        // ---- phase 4: M = I + eps*G^T G (upper tiles only, mirrored) ; w = G^T s on idle warps ----
        if (has_tile) {
            int p0 = tp_s * 4, q0 = tq_s * 4;
            float acc[4][4];
            #pragma unroll
            for (int a = 0; a < 4; a++)
                #pragma unroll
                for (int bb = 0; bb < 4; bb++) acc[a][bb] = 0.f;
            for (int h = 0; h < 128; h++) {
                float4 gp = *(const float4*)(Gs + h * GS_STRIDE + p0);
                float4 gq = *(const float4*)(Gs + h * GS_STRIDE + q0);
                acc[0][0] += gp.x * gq.x; acc[0][1] += gp.x * gq.y; acc[0][2] += gp.x * gq.z; acc[0][3] += gp.x * gq.w;
                acc[1][0] += gp.y * gq.x; acc[1][1] += gp.y * gq.y; acc[1][2] += gp.y * gq.z; acc[1][3] += gp.y * gq.w;
                acc[2][0] += gp.z * gq.x; acc[2][1] += gp.z * gq.y; acc[2][2] += gp.z * gq.z; acc[2][3] += gp.z * gq.w;
                acc[3][0] += gp.w * gq.x; acc[3][1] += gp.w * gq.y; acc[3][2] += gp.w * gq.z; acc[3][3] += gp.w * gq.w;
            }
            #pragma unroll
            for (int a = 0; a < 4; a++)
                #pragma unroll
                for (int bb = 0; bb < 4; bb++) {
                    float v = EPSP * acc[a][bb] + ((p0 + a) == (q0 + bb) ? 1.f : 0.f);
                    Ms[(p0 + a) * MS_STRIDE + (q0 + bb)] = v;
                    Ms[(q0 + bb) * MS_STRIDE + (p0 + a)] = v;
                }
        } else if (tid >= 192) {
            int e = tid - 192;
            float acc = 0.f;
            for (int h = 0; h < 128; h++) acc += Gs[h * GS_STRIDE + e] * s_s[h];
            wv[e] = acc;
        }
        __syncthreads();

        // ---- panel-blocked LDL^T (8 panels of 8 cols) ----
        #pragma unroll 1
        for (int pp = 0; pp < 8; pp++) {
            int p0 = pp * 8;
            // phase A: warp 0 factors the 64x8 panel + forward solve
            if (warp == 0) {
                int j0 = p0 + lane;
                int j1 = p0 + 32 + lane;
                #pragma unroll 1
                for (int kl = 0; kl < 8; kl++) {
                    int k = p0 + kl;
                    float invd = __fdividef(1.0f, Ms[k * MS_STRIDE + k]);
                    if (lane == 0) dinv[k] = invd;
                    if (j0 > k && j0 < 64) {
                        float lv = Ms[j0 * MS_STRIDE + k] * invd;
                        Ln[j0 * MS_STRIDE + k] = lv;
                        wv[j0] -= lv * wv[k];
                        for (int c = kl + 1; c < 8; c++)
                            Ms[j0 * MS_STRIDE + p0 + c] -= lv * Ms[k * MS_STRIDE + p0 + c];
                    }
                    if (j1 < 64) {
                        float lv = Ms[j1 * MS_STRIDE + k] * invd;
                        Ln[j1 * MS_STRIDE + k] = lv;
                        wv[j1] -= lv * wv[k];
                        for (int c = kl + 1; c < 8; c++)
                            Ms[j1 * MS_STRIDE + p0 + c] -= lv * Ms[k * MS_STRIDE + p0 + c];
                    }
                    __syncwarp();
                }
            }
            __syncthreads();
            // phase B: rank-8 trailing update, L-rows register-hoisted
            int r0 = p0 + 8;
            int R = 64 - r0;
            if (R > 0) {
                for (int jq = warp; jq * 4 < R; jq += 8) {
                    int jb = r0 + jq * 4;
                    float lr[4][8];
                    #pragma unroll
                    for (int u = 0; u < 4; u++)
                        #pragma unroll
                        for (int c = 0; c < 8; c++)
                            lr[u][c] = Ln[(jb + u) * MS_STRIDE + p0 + c];
                    for (int i = r0 + lane; i < 64; i += 32) {
                        float a0 = Ms[i * MS_STRIDE + p0 + 0];
                        float a1 = Ms[i * MS_STRIDE + p0 + 1];
                        float a2 = Ms[i * MS_STRIDE + p0 + 2];
                        float a3 = Ms[i * MS_STRIDE + p0 + 3];
                        float a4 = Ms[i * MS_STRIDE + p0 + 4];
                        float a5 = Ms[i * MS_STRIDE + p0 + 5];
                        float a6 = Ms[i * MS_STRIDE + p0 + 6];
                        float a7 = Ms[i * MS_STRIDE + p0 + 7];
                        #pragma unroll
                        for (int u = 0; u < 4; u++) {
                            int j = jb + u;
                            float acc = Ms[j * MS_STRIDE + i];
                            acc -= lr[u][0] * a0 + lr[u][1] * a1 + lr[u][2] * a2 + lr[u][3] * a3
                                 + lr[u][4] * a4 + lr[u][5] * a5 + lr[u][6] * a6 + lr[u][7] * a7;
                            Ms[j * MS_STRIDE + i] = acc;
                        }
                    }
                }
                __syncthreads();
            }
        }

        // ---- back solve (warp 0, register-resident) ----
        if (warp == 0) {
            float x0 = wv[lane] * dinv[lane];
            float x1 = wv[lane + 32] * dinv[lane + 32];
            #pragma unroll 1
            for (int k = 63; k >= 32; k--) {
                float xk = __shfl_sync(FULLM, x1, k - 32);
                if (lane + 32 < k) x1 -= Ln[k * MS_STRIDE + lane + 32] * xk;
                x0 -= Ln[k * MS_STRIDE + lane] * xk;
            }
            #pragma unroll 1
            for (int k = 31; k >= 1; k--) {
                float xk = __shfl_sync(FULLM, x0, k);
                if (lane < k) x0 -= Ln[k * MS_STRIDE + lane] * xk;
            }
            wv[lane] = x0;
            wv[lane + 32] = x1;
        }
        __syncthreads();

        // ---- epilogue: c = s - eps*G*x ; h = o*tanh(c) ----
        if (tid < 128) {
            const float4* gr = (const float4*)(Gs + tid * GS_STRIDE);
            const float4* wr = (const float4*)wv;
            float acc = 0.f;
            #pragma unroll
            for (int q = 0; q < 16; q++) {
                float4 g4 = gr[q];
                float4 w4 = wr[q];
                acc += g4.x * w4.x + g4.y * w4.y + g4.z * w4.z + g4.w * w4.w;
            }
            float cn = s_s[tid] - EPSP * acc;
            c_sm[tid] = cn;
            h_sm[tid] = o_s[tid] * tanhf(cn);
        }
        __syncthreads();
    }

    // ---- final linear ----
    if (tid < ODIM) {
        float acc = lin_b[tid];
        for (int k = 0; k < 128; k++) acc += h_sm[k] * lin_w[tid * 128 + k];
        out[b * ODIM + tid] = acc;
    }
}

extern "C" void kernel_launch(void* const* d_in, const int* in_sizes, int n_in,
                              void* d_out, int out_size) {
    const float* inputs  = (const float*)d_in[0];
    const float* conv_w  = (const float*)d_in[2];
    const float* conv_b  = (const float*)d_in[3];
    const float* bn_g    = (const float*)d_in[4];
    const float* bn_b    = (const float*)d_in[5];
    const float* w_ih    = (const float*)d_in[6];
    const float* w_hh    = (const float*)d_in[7];
    const float* b_ih    = (const float*)d_in[8];
    const float* b_hh    = (const float*)d_in[9];
    const float* lin_w   = (const float*)d_in[10];
    const float* lin_b   = (const float*)d_in[11];
    float* out = (float*)d_out;

    cudaFuncSetAttribute(k4_scan, cudaFuncAttributeMaxDynamicSharedMemorySize, 73728);

    k0_prep<<<483, 256>>>(w_ih, w_hh, b_ih, b_hh, conv_w);
    k1_conv<<<1024, 256>>>(inputs, conv_b);
    k2a_stats<<<256, 256>>>();
    k2b_finalize<<<1, 64>>>(bn_g, bn_b);
    k3_zx<<<2048, 256>>>();
    k4_scan<<<64, 256, 73728>>>(lin_w, lin_b, w_ih, out);
}

// round 11
// speedup vs baseline: 1.7947x; 1.5752x over previous
#include <cuda_runtime.h>
#include <cuda_bf16.h>
#include <cstdint>
#include <math.h>

#define BDIM 64
#define TDIM 768
#define DDIM 128
#define EDIM 64
#define HDIM 128
#define ODIM 10
#define TC   256
#define G4   512
#define EPSP 5.0f
#define FULLM 0xffffffffu

__device__ __align__(16) float g_emb[BDIM * TC * EDIM];
__device__ __align__(16) float g_zx[(size_t)BDIM * TC * G4];
__device__ __align__(16) float g_whhT[HDIM * G4];
__device__ __align__(16) float g_wihT[EDIM * G4];
__device__ __align__(16) float g_convW[384 * EDIM];
__device__ __align__(16) float g_bias[G4];
__device__ float g_part_s[256 * EDIM];
__device__ float g_part_ss[256 * EDIM];
__device__ float g_scale[EDIM];
__device__ float g_shift[EDIM];

__device__ __forceinline__ float sigf(float x) { return 1.0f / (1.0f + expf(-x)); }

__device__ __forceinline__ unsigned long long pk2(float lo, float hi) {
    unsigned long long d; asm("mov.b64 %0, {%1,%2};" : "=l"(d) : "f"(lo), "f"(hi)); return d;
}
__device__ __forceinline__ void upk2(unsigned long long v, float& lo, float& hi) {
    asm("mov.b64 {%0,%1}, %2;" : "=f"(lo), "=f"(hi) : "l"(v));
}
__device__ __forceinline__ unsigned long long fma2(unsigned long long a, unsigned long long b, unsigned long long c) {
    unsigned long long d; asm("fma.rn.f32x2 %0, %1, %2, %3;" : "=l"(d) : "l"(a), "l"(b), "l"(c)); return d;
}

// ---------------- K0 ----------------
__global__ __launch_bounds__(256) void k0_prep(
    const float* __restrict__ wih, const float* __restrict__ whh,
    const float* __restrict__ bih, const float* __restrict__ bhh,
    const float* __restrict__ conv_w) {
    int i = blockIdx.x * 256 + threadIdx.x;
    if (i < 65536) {
        int h = i >> 9, j = i & 511;
        g_whhT[i] = whh[j * HDIM + h];
    } else if (i < 65536 + 32768) {
        int m = i - 65536;
        int e = m >> 9, j = m & 511;
        g_wihT[m] = wih[j * EDIM + e];
    } else if (i < 65536 + 32768 + 24576) {
        int m = i - 65536 - 32768;
        int q = m >> 6, e = m & 63;
        int k = q >> 7, d = q & 127;
        g_convW[m] = conv_w[e * 384 + d * 3 + k];
    } else if (i < 65536 + 32768 + 24576 + 512) {
        int j = i - 65536 - 32768 - 24576;
        g_bias[j] = bih[j] + bhh[j];
    }
}

// ---------------- K1 ----------------
__global__ __launch_bounds__(256) void k1_conv(
    const float* __restrict__ in, const float* __restrict__ conv_b) {
    __shared__ float xn[48 * 128];
    __shared__ float invn[48];
    int tid = threadIdx.x;
    int b = blockIdx.x >> 4, seg = blockIdx.x & 15;

    const float4* src = (const float4*)(in + ((size_t)b * TDIM + seg * 48) * DDIM);
    float4* d4 = (float4*)xn;
    for (int i = tid; i < 1536; i += 256) d4[i] = src[i];
    __syncthreads();

    int warp = tid >> 5, lane = tid & 31;
    for (int r = warp; r < 48; r += 8) {
        float v = 0.f;
        #pragma unroll
        for (int q = 0; q < 4; q++) { float x = xn[r * 128 + lane + q * 32]; v += x * x; }
        #pragma unroll
        for (int off = 16; off; off >>= 1) v += __shfl_down_sync(FULLM, v, off);
        if (lane == 0) invn[r] = 1.0f / fmaxf(sqrtf(v), 1e-12f);
    }
    __syncthreads();
    for (int i = tid; i < 6144; i += 256) xn[i] *= invn[i >> 7];
    __syncthreads();

    int e = tid & 63, rg = tid >> 6;
    float acc0 = 0.f, acc1 = 0.f, acc2 = 0.f, acc3 = 0.f;
    const float* xr = xn + rg * 4 * 384;
    for (int q = 0; q < 384; q++) {
        float wv = g_convW[q * 64 + e];
        acc0 += xr[q] * wv;
        acc1 += xr[q + 384] * wv;
        acc2 += xr[q + 768] * wv;
        acc3 += xr[q + 1152] * wv;
    }
    float cb = conv_b[e];
    int row0 = b * TC + seg * 16 + rg * 4;
    g_emb[(row0 + 0) * 64 + e] = acc0 + cb;
    g_emb[(row0 + 1) * 64 + e] = acc1 + cb;
    g_emb[(row0 + 2) * 64 + e] = acc2 + cb;
    g_emb[(row0 + 3) * 64 + e] = acc3 + cb;
}

// ---------------- K2a/K2b ----------------
__global__ __launch_bounds__(256) void k2a_stats() {
    __shared__ float ps[256], pss[256];
    int tid = threadIdx.x;
    int r0 = blockIdx.x * 64;
    int e = tid & 63, qr = tid >> 6;
    float s = 0.f, ss = 0.f;
    for (int u = 0; u < 16; u++) {
        float v = g_emb[(r0 + qr * 16 + u) * 64 + e];
        s += v; ss += v * v;
    }
    ps[tid] = s; pss[tid] = ss;
    __syncthreads();
    if (tid < 64) {
        s  = ps[tid]  + ps[tid + 64]  + ps[tid + 128]  + ps[tid + 192];
        ss = pss[tid] + pss[tid + 64] + pss[tid + 128] + pss[tid + 192];
        g_part_s[blockIdx.x * 64 + tid] = s;
        g_part_ss[blockIdx.x * 64 + tid] = ss;
    }
}

__global__ __launch_bounds__(64) void k2b_finalize(
    const float* __restrict__ gamma, const float* __restrict__ beta) {
    int e = threadIdx.x;
    float s = 0.f, ss = 0.f;
    for (int blk = 0; blk < 256; blk++) {
        s  += g_part_s[blk * 64 + e];
        ss += g_part_ss[blk * 64 + e];
    }
    const float inv_n = 1.0f / 16384.0f;
    float mean = s * inv_n;
    float var = ss * inv_n - mean * mean;
    float sc = gamma[e] * rsqrtf(var + 1e-5f);
    g_scale[e] = sc;
    g_shift[e] = beta[e] - mean * sc;
}

// ---------------- K3 ----------------
__global__ __launch_bounds__(256) void k3_zx() {
    __shared__ float act[512];
    int tid = threadIdx.x;
    int r0 = blockIdx.x * 8;
    for (int i = tid; i < 512; i += 256) {
        int rr = i >> 6, e = i & 63;
        float a = g_emb[(r0 + rr) * 64 + e];
        act[i] = fmaxf(a * g_scale[e] + g_shift[e], 0.f);
    }
    __syncthreads();
    int j0 = tid, j1 = tid + 256;
    float acc0[8], acc1[8];
    float b0 = g_bias[j0], b1 = g_bias[j1];
    #pragma unroll
    for (int u = 0; u < 8; u++) { acc0[u] = b0; acc1[u] = b1; }
    for (int e = 0; e < 64; e++) {
        float w0 = g_wihT[e * 512 + j0];
        float w1 = g_wihT[e * 512 + j1];
        #pragma unroll
        for (int u = 0; u < 8; u++) {
            float a = act[u * 64 + e];
            acc0[u] += a * w0;
            acc1[u] += a * w1;
        }
    }
    #pragma unroll
    for (int u = 0; u < 8; u++) {
        float* zr = g_zx + ((size_t)(r0 + u)) * 512;
        zr[j0] = acc0[u];
        zr[j1] = acc1[u];
    }
}

// ---------------- K4: recurrent scan ----------------
#define GS_STRIDE 68
#define MS_STRIDE 65
__global__ __launch_bounds__(256) void k4_scan(
    const float* __restrict__ lin_w, const float* __restrict__ lin_b,
    const float* __restrict__ wih, float* __restrict__ out) {
    extern __shared__ float sm[];
    float* Gs  = sm;                 // 128*68 = 8704
    float* Ms  = sm + 8704;          // 64*65
    float* Ln  = sm + 12864;         // 64*65
    float* i_s = sm + 17024;
    float* f_s = sm + 17152;
    float* gg_s= sm + 17280;
    float* o_s = sm + 17408;
    float* s_s = sm + 17536;
    float* ai  = sm + 17664;
    float* af  = sm + 17792;
    float* ag  = sm + 17920;
    float* h_sm= sm + 18048;
    float* c_sm= sm + 18176;
    float* wv  = sm + 18304;
    float* dinv= sm + 18368;
    float* ti  = sm + 18432;
    float* tf  = sm + 18560;
    float* tg  = sm + 18688;
    float* dval= sm + 18816;         // end 18880 floats = 75520 B

    int tid = threadIdx.x;
    int b = blockIdx.x;
    int warp = tid >> 5, lane = tid & 31;

    if (tid < 128) { h_sm[tid] = 0.f; c_sm[tid] = 0.f; }
    __syncthreads();

    for (int t = 0; t < TC; t++) {
        // ---- phase 1: z = zx + h @ whhT ; gates ----
        {
            const float* zrow = g_zx + ((size_t)(b * TC + t)) * 512;
            float2 zz = *(const float2*)(zrow + 2 * tid);
            float a0 = zz.x, a1 = zz.y;
            const float2* wbase = (const float2*)g_whhT + tid;
            #pragma unroll 4
            for (int hh = 0; hh < 128; hh += 4) {
                float4 hv = *(const float4*)(h_sm + hh);
                float2 w0 = wbase[(hh + 0) * 256];
                float2 w1 = wbase[(hh + 1) * 256];
                float2 w2 = wbase[(hh + 2) * 256];
                float2 w3 = wbase[(hh + 3) * 256];
                a0 += hv.x * w0.x; a1 += hv.x * w0.y;
                a0 += hv.y * w1.x; a1 += hv.y * w1.y;
                a0 += hv.z * w2.x; a1 += hv.z * w2.y;
                a0 += hv.w * w3.x; a1 += hv.w * w3.y;
            }
            int gsel = tid >> 6, hh2 = (tid & 63) * 2;
            if (gsel == 0)      { i_s[hh2]  = sigf(a0);  i_s[hh2 + 1]  = sigf(a1); }
            else if (gsel == 1) { f_s[hh2]  = sigf(a0);  f_s[hh2 + 1]  = sigf(a1); }
            else if (gsel == 2) { gg_s[hh2] = tanhf(a0); gg_s[hh2 + 1] = tanhf(a1); }
            else                { o_s[hh2]  = sigf(a0);  o_s[hh2 + 1]  = sigf(a1); }
        }
        __syncthreads();

        // ---- phase 2: s, Jacobian coefficients, t-vectors ----
        if (tid < 128) {
            float iv = i_s[tid], fv = f_s[tid], gv = gg_s[tid], cv = c_sm[tid];
            float sv = fv * cv + iv * gv;
            float a1v = iv * (1.f - iv) * gv;
            float a2v = fv * (1.f - fv) * cv;
            float a3v = iv * (1.f - gv * gv);
            s_s[tid] = sv;
            ai[tid] = a1v; af[tid] = a2v; ag[tid] = a3v;
            ti[tid] = a1v * sv; tf[tid] = a2v * sv; tg[tid] = a3v * sv;
        }
        __syncthreads();

        // ---- phase 3: G build (192 thr) + w = G^T s via t-vectors (64 thr) ----
        if (tid < 192) {
            for (int idx = tid; idx < 8192; idx += 192) {
                int h = idx >> 6, e = idx & 63;
                Gs[h * GS_STRIDE + e] = ai[h] * wih[h * 64 + e]
                                      + af[h] * wih[(128 + h) * 64 + e]
                                      + ag[h] * wih[(256 + h) * 64 + e];
            }
        } else {
            int e = tid - 192;
            float acc = 0.f;
            for (int h = 0; h < 128; h++)
                acc += ti[h] * wih[h * 64 + e]
                     + tf[h] * wih[(128 + h) * 64 + e]
                     + tg[h] * wih[(256 + h) * 64 + e];
            wv[e] = acc;
        }
        __syncthreads();

        // ---- phase 4: M = I + eps*G^T G, full tiles, f32x2 packed FMA ----
        {
            int tp = tid >> 4, tq = tid & 15;
            int pm = tp * 4, qm = tq * 4;
            unsigned long long acc01[4] = {0ULL,0ULL,0ULL,0ULL};
            unsigned long long acc23[4] = {0ULL,0ULL,0ULL,0ULL};
            for (int h = 0; h < 128; h++) {
                float4 gp = *(const float4*)(Gs + h * GS_STRIDE + pm);
                float4 gq = *(const float4*)(Gs + h * GS_STRIDE + qm);
                unsigned long long q01 = pk2(gq.x, gq.y), q23 = pk2(gq.z, gq.w);
                unsigned long long px = pk2(gp.x, gp.x);
                unsigned long long py = pk2(gp.y, gp.y);
                unsigned long long pz = pk2(gp.z, gp.z);
                unsigned long long pw = pk2(gp.w, gp.w);
                acc01[0] = fma2(px, q01, acc01[0]); acc23[0] = fma2(px, q23, acc23[0]);
                acc01[1] = fma2(py, q01, acc01[1]); acc23[1] = fma2(py, q23, acc23[1]);
                acc01[2] = fma2(pz, q01, acc01[2]); acc23[2] = fma2(pz, q23, acc23[2]);
                acc01[3] = fma2(pw, q01, acc01[3]); acc23[3] = fma2(pw, q23, acc23[3]);
            }
            #pragma unroll
            for (int a = 0; a < 4; a++) {
                float m0, m1, m2, m3;
                upk2(acc01[a], m0, m1);
                upk2(acc23[a], m2, m3);
                int ri = pm + a;
                float* mr = Ms + ri * MS_STRIDE + qm;
                mr[0] = EPSP * m0 + (ri == qm + 0 ? 1.f : 0.f);
                mr[1] = EPSP * m1 + (ri == qm + 1 ? 1.f : 0.f);
                mr[2] = EPSP * m2 + (ri == qm + 2 ? 1.f : 0.f);
                mr[3] = EPSP * m3 + (ri == qm + 3 ? 1.f : 0.f);
            }
        }
        __syncthreads();

        // ---- panel LDL^T: phase A register-resident on warp 0 ----
        #pragma unroll 1
        for (int pp = 0; pp < 8; pp++) {
            int p0 = pp * 8;
            if (warp == 0) {
                int row0 = p0 + lane;
                int row1 = p0 + 32 + lane;
                bool act0 = row0 < 64;
                bool act1 = row1 < 64;
                float r0c[8], r1c[8], v0 = 0.f, v1 = 0.f;
                if (act0) {
                    #pragma unroll
                    for (int c = 0; c < 8; c++) r0c[c] = Ms[row0 * MS_STRIDE + p0 + c];
                    v0 = wv[row0];
                }
                if (act1) {
                    #pragma unroll
                    for (int c = 0; c < 8; c++) r1c[c] = Ms[row1 * MS_STRIDE + p0 + c];
                    v1 = wv[row1];
                }
                #pragma unroll
                for (int kl = 0; kl < 8; kl++) {
                    int k = p0 + kl;
                    float dk = __shfl_sync(FULLM, r0c[kl], kl);
                    float vk = __shfl_sync(FULLM, v0, kl);
                    float piv[8];
                    #pragma unroll
                    for (int c = 0; c < 8; c++) piv[c] = __shfl_sync(FULLM, r0c[c], kl);
                    float invd = __fdividef(1.0f, dk);
                    if (lane == kl) { dinv[k] = invd; dval[k] = dk; }
                    if (act0 && row0 > k) {
                        float lv = r0c[kl] * invd;
                        Ln[row0 * MS_STRIDE + k] = lv;
                        v0 -= lv * vk;
                        #pragma unroll
                        for (int c = 0; c < 8; c++) if (c > kl) r0c[c] -= lv * piv[c];
                    }
                    if (act1) {
                        float lv = r1c[kl] * invd;
                        Ln[row1 * MS_STRIDE + k] = lv;
                        v1 -= lv * vk;
                        #pragma unroll
                        for (int c = 0; c < 8; c++) if (c > kl) r1c[c] -= lv * piv[c];
                    }
                }
                if (act0) wv[row0] = v0;
                if (act1) wv[row1] = v1;
            }
            __syncthreads();

            // phase B: rank-8 trailing update from Ln (d folded into hoisted rows)
            int r0 = p0 + 8;
            if (r0 < 64) {
                for (int jq = warp; jq * 4 < 64 - r0; jq += 8) {
                    int jb = r0 + jq * 4;
                    float lrd[4][8];
                    #pragma unroll
                    for (int u = 0; u < 4; u++)
                        #pragma unroll
                        for (int c = 0; c < 8; c++)
                            lrd[u][c] = Ln[(jb + u) * MS_STRIDE + p0 + c] * dval[p0 + c];
                    for (int i = r0 + lane; i < 64; i += 32) {
                        float a[8];
                        #pragma unroll
                        for (int c = 0; c < 8; c++) a[c] = Ln[i * MS_STRIDE + p0 + c];
                        #pragma unroll
                        for (int u = 0; u < 4; u++) {
                            int j = jb + u;
                            float acc = Ms[j * MS_STRIDE + i];
                            #pragma unroll
                            for (int c = 0; c < 8; c++) acc -= lrd[u][c] * a[c];
                            Ms[j * MS_STRIDE + i] = acc;
                        }
                    }
                }
                __syncthreads();
            }
        }

        // ---- back solve (warp 0, register-resident) ----
        if (warp == 0) {
            float x0 = wv[lane] * dinv[lane];
            float x1 = wv[lane + 32] * dinv[lane + 32];
            #pragma unroll 1
            for (int k = 63; k >= 32; k--) {
                float xk = __shfl_sync(FULLM, x1, k - 32);
                if (lane + 32 < k) x1 -= Ln[k * MS_STRIDE + lane + 32] * xk;
                x0 -= Ln[k * MS_STRIDE + lane] * xk;
            }
            #pragma unroll 1
            for (int k = 31; k >= 1; k--) {
                float xk = __shfl_sync(FULLM, x0, k);
                if (lane < k) x0 -= Ln[k * MS_STRIDE + lane] * xk;
            }
            wv[lane] = x0;
            wv[lane + 32] = x1;
        }
        __syncthreads();

        // ---- epilogue: c = s - eps*G*x ; h = o*tanh(c) ----
        if (tid < 128) {
            const float4* gr = (const float4*)(Gs + tid * GS_STRIDE);
            const float4* wr = (const float4*)wv;
            float acc = 0.f;
            #pragma unroll
            for (int q = 0; q < 16; q++) {
                float4 g4 = gr[q];
                float4 w4 = wr[q];
                acc += g4.x * w4.x + g4.y * w4.y + g4.z * w4.z + g4.w * w4.w;
            }
            float cn = s_s[tid] - EPSP * acc;
            c_sm[tid] = cn;
            h_sm[tid] = o_s[tid] * tanhf(cn);
        }
        __syncthreads();
    }

    if (tid < ODIM) {
        float acc = lin_b[tid];
        for (int k = 0; k < 128; k++) acc += h_sm[k] * lin_w[tid * 128 + k];
        out[b * ODIM + tid] = acc;
    }
}

extern "C" void kernel_launch(void* const* d_in, const int* in_sizes, int n_in,
                              void* d_out, int out_size) {
    const float* inputs  = (const float*)d_in[0];
    const float* conv_w  = (const float*)d_in[2];
    const float* conv_b  = (const float*)d_in[3];
    const float* bn_g    = (const float*)d_in[4];
    const float* bn_b    = (const float*)d_in[5];
    const float* w_ih    = (const float*)d_in[6];
    const float* w_hh    = (const float*)d_in[7];
    const float* b_ih    = (const float*)d_in[8];
    const float* b_hh    = (const float*)d_in[9];
    const float* lin_w   = (const float*)d_in[10];
    const float* lin_b   = (const float*)d_in[11];
    float* out = (float*)d_out;

    cudaFuncSetAttribute(k4_scan, cudaFuncAttributeMaxDynamicSharedMemorySize, 75520);

    k0_prep<<<483, 256>>>(w_ih, w_hh, b_ih, b_hh, conv_w);
    k1_conv<<<1024, 256>>>(inputs, conv_b);
    k2a_stats<<<256, 256>>>();
    k2b_finalize<<<1, 64>>>(bn_g, bn_b);
    k3_zx<<<2048, 256>>>();
    k4_scan<<<64, 256, 75520>>>(lin_w, lin_b, w_ih, out);
}

// round 12
// speedup vs baseline: 2.2346x; 1.2451x over previous
#include <cuda_runtime.h>
#include <cuda_bf16.h>
#include <cstdint>
#include <math.h>

#define BDIM 64
#define TDIM 768
#define DDIM 128
#define EDIM 64
#define HDIM 128
#define ODIM 10
#define TC   256
#define G4   512
#define EPSP 5.0f
#define FULLM 0xffffffffu

__device__ __align__(16) float g_emb[BDIM * TC * EDIM];
__device__ __align__(16) float g_zx[(size_t)BDIM * TC * G4];
__device__ __align__(16) float g_whhT[HDIM * G4];
__device__ __align__(16) float g_wihT[EDIM * G4];
__device__ __align__(16) float g_convW[384 * EDIM];
__device__ __align__(16) float g_bias[G4];
__device__ float g_part_s[256 * EDIM];
__device__ float g_part_ss[256 * EDIM];
__device__ float g_scale[EDIM];
__device__ float g_shift[EDIM];

__device__ __forceinline__ float sigf(float x) { return 1.0f / (1.0f + expf(-x)); }

__device__ __forceinline__ unsigned long long pk2(float lo, float hi) {
    unsigned long long d; asm("mov.b64 %0, {%1,%2};" : "=l"(d) : "f"(lo), "f"(hi)); return d;
}
__device__ __forceinline__ void upk2(unsigned long long v, float& lo, float& hi) {
    asm("mov.b64 {%0,%1}, %2;" : "=f"(lo), "=f"(hi) : "l"(v));
}
__device__ __forceinline__ unsigned long long fma2(unsigned long long a, unsigned long long b, unsigned long long c) {
    unsigned long long d; asm("fma.rn.f32x2 %0, %1, %2, %3;" : "=l"(d) : "l"(a), "l"(b), "l"(c)); return d;
}

// ---------------- K0 ----------------
__global__ __launch_bounds__(256) void k0_prep(
    const float* __restrict__ wih, const float* __restrict__ whh,
    const float* __restrict__ bih, const float* __restrict__ bhh,
    const float* __restrict__ conv_w) {
    int i = blockIdx.x * 256 + threadIdx.x;
    if (i < 65536) {
        int h = i >> 9, j = i & 511;
        g_whhT[i] = whh[j * HDIM + h];
    } else if (i < 65536 + 32768) {
        int m = i - 65536;
        int e = m >> 9, j = m & 511;
        g_wihT[m] = wih[j * EDIM + e];
    } else if (i < 65536 + 32768 + 24576) {
        int m = i - 65536 - 32768;
        int q = m >> 6, e = m & 63;
        int k = q >> 7, d = q & 127;
        g_convW[m] = conv_w[e * 384 + d * 3 + k];
    } else if (i < 65536 + 32768 + 24576 + 512) {
        int j = i - 65536 - 32768 - 24576;
        g_bias[j] = bih[j] + bhh[j];
    }
}

// ---------------- K1 ----------------
__global__ __launch_bounds__(256) void k1_conv(
    const float* __restrict__ in, const float* __restrict__ conv_b) {
    __shared__ float xn[48 * 128];
    __shared__ float invn[48];
    int tid = threadIdx.x;
    int b = blockIdx.x >> 4, seg = blockIdx.x & 15;

    const float4* src = (const float4*)(in + ((size_t)b * TDIM + seg * 48) * DDIM);
    float4* d4 = (float4*)xn;
    for (int i = tid; i < 1536; i += 256) d4[i] = src[i];
    __syncthreads();

    int warp = tid >> 5, lane = tid & 31;
    for (int r = warp; r < 48; r += 8) {
        float v = 0.f;
        #pragma unroll
        for (int q = 0; q < 4; q++) { float x = xn[r * 128 + lane + q * 32]; v += x * x; }
        #pragma unroll
        for (int off = 16; off; off >>= 1) v += __shfl_down_sync(FULLM, v, off);
        if (lane == 0) invn[r] = 1.0f / fmaxf(sqrtf(v), 1e-12f);
    }
    __syncthreads();
    for (int i = tid; i < 6144; i += 256) xn[i] *= invn[i >> 7];
    __syncthreads();

    int e = tid & 63, rg = tid >> 6;
    float acc0 = 0.f, acc1 = 0.f, acc2 = 0.f, acc3 = 0.f;
    const float* xr = xn + rg * 4 * 384;
    for (int q = 0; q < 384; q++) {
        float wv = g_convW[q * 64 + e];
        acc0 += xr[q] * wv;
        acc1 += xr[q + 384] * wv;
        acc2 += xr[q + 768] * wv;
        acc3 += xr[q + 1152] * wv;
    }
    float cb = conv_b[e];
    int row0 = b * TC + seg * 16 + rg * 4;
    g_emb[(row0 + 0) * 64 + e] = acc0 + cb;
    g_emb[(row0 + 1) * 64 + e] = acc1 + cb;
    g_emb[(row0 + 2) * 64 + e] = acc2 + cb;
    g_emb[(row0 + 3) * 64 + e] = acc3 + cb;
}

// ---------------- K2a/K2b ----------------
__global__ __launch_bounds__(256) void k2a_stats() {
    __shared__ float ps[256], pss[256];
    int tid = threadIdx.x;
    int r0 = blockIdx.x * 64;
    int e = tid & 63, qr = tid >> 6;
    float s = 0.f, ss = 0.f;
    for (int u = 0; u < 16; u++) {
        float v = g_emb[(r0 + qr * 16 + u) * 64 + e];
        s += v; ss += v * v;
    }
    ps[tid] = s; pss[tid] = ss;
    __syncthreads();
    if (tid < 64) {
        s  = ps[tid]  + ps[tid + 64]  + ps[tid + 128]  + ps[tid + 192];
        ss = pss[tid] + pss[tid + 64] + pss[tid + 128] + pss[tid + 192];
        g_part_s[blockIdx.x * 64 + tid] = s;
        g_part_ss[blockIdx.x * 64 + tid] = ss;
    }
}

__global__ __launch_bounds__(64) void k2b_finalize(
    const float* __restrict__ gamma, const float* __restrict__ beta) {
    int e = threadIdx.x;
    float s = 0.f, ss = 0.f;
    for (int blk = 0; blk < 256; blk++) {
        s  += g_part_s[blk * 64 + e];
        ss += g_part_ss[blk * 64 + e];
    }
    const float inv_n = 1.0f / 16384.0f;
    float mean = s * inv_n;
    float var = ss * inv_n - mean * mean;
    float sc = gamma[e] * rsqrtf(var + 1e-5f);
    g_scale[e] = sc;
    g_shift[e] = beta[e] - mean * sc;
}

// ---------------- K3 ----------------
__global__ __launch_bounds__(256) void k3_zx() {
    __shared__ float act[512];
    int tid = threadIdx.x;
    int r0 = blockIdx.x * 8;
    for (int i = tid; i < 512; i += 256) {
        int rr = i >> 6, e = i & 63;
        float a = g_emb[(r0 + rr) * 64 + e];
        act[i] = fmaxf(a * g_scale[e] + g_shift[e], 0.f);
    }
    __syncthreads();
    int j0 = tid, j1 = tid + 256;
    float acc0[8], acc1[8];
    float b0 = g_bias[j0], b1 = g_bias[j1];
    #pragma unroll
    for (int u = 0; u < 8; u++) { acc0[u] = b0; acc1[u] = b1; }
    for (int e = 0; e < 64; e++) {
        float w0 = g_wihT[e * 512 + j0];
        float w1 = g_wihT[e * 512 + j1];
        #pragma unroll
        for (int u = 0; u < 8; u++) {
            float a = act[u * 64 + e];
            acc0[u] += a * w0;
            acc1[u] += a * w1;
        }
    }
    #pragma unroll
    for (int u = 0; u < 8; u++) {
        float* zr = g_zx + ((size_t)(r0 + u)) * 512;
        zr[j0] = acc0[u];
        zr[j1] = acc1[u];
    }
}

// ---------------- K4: recurrent scan (512 threads) ----------------
#define GS_STRIDE 68
#define MS_STRIDE 65
__global__ __launch_bounds__(512) void k4_scan(
    const float* __restrict__ lin_w, const float* __restrict__ lin_b,
    const float* __restrict__ wih, float* __restrict__ out) {
    extern __shared__ float sm[];
    float* Gs  = sm;                 // 128*68 = 8704
    float* Ms  = sm + 8704;          // 64*65 = 4160  (aliased as ph1 partial buf)
    float* Ln  = sm + 12864;         // 64*65
    float* i_s = sm + 17024;
    float* f_s = sm + 17152;
    float* gg_s= sm + 17280;
    float* o_s = sm + 17408;
    float* s_s = sm + 17536;
    float* ai  = sm + 17664;
    float* af  = sm + 17792;
    float* ag  = sm + 17920;
    float* h_sm= sm + 18048;
    float* c_sm= sm + 18176;
    float* wv  = sm + 18304;
    float* dinv= sm + 18368;
    float* dval= sm + 18432;         // end 18496 floats = 73984 B

    int tid = threadIdx.x;
    int b = blockIdx.x;
    int warp = tid >> 5, lane = tid & 31;

    // triangular 4x2 tile map: 16 p-tiles x 32 q-tiles, keep tq >= 2*tp (272 tiles)
    int tp_s = 0, tq_s = 0; bool has_tile = false;
    {
        int idx = tid;
        #pragma unroll 1
        for (int p = 0; p < 16; p++) {
            int wdt = 32 - 2 * p;
            if (idx < wdt) { tp_s = p; tq_s = 2 * p + idx; has_tile = true; break; }
            idx -= wdt;
        }
    }

    if (tid < 128) { h_sm[tid] = 0.f; c_sm[tid] = 0.f; }
    __syncthreads();

    for (int t = 0; t < TC; t++) {
        // ---- phase 1: z = zx + h @ whhT, split (j-quad x h-quarter) ----
        {
            int jq = tid & 127, quarter = tid >> 7;
            float4 zz4 = make_float4(0.f, 0.f, 0.f, 0.f);
            if (quarter == 0)
                zz4 = ((const float4*)(g_zx + ((size_t)(b * TC + t)) * 512))[jq];
            float4 acc = make_float4(0.f, 0.f, 0.f, 0.f);
            const float4* w4 = (const float4*)g_whhT + jq;  // row stride 128 float4
            int h0 = quarter * 32;
            #pragma unroll 8
            for (int hh = 0; hh < 32; hh++) {
                float hv = h_sm[h0 + hh];
                float4 w = w4[(h0 + hh) * 128];
                acc.x += hv * w.x; acc.y += hv * w.y;
                acc.z += hv * w.z; acc.w += hv * w.w;
            }
            float4* buf = (float4*)Ms;  // alias: Ms dead here
            if (quarter > 0) buf[(quarter - 1) * 128 + jq] = acc;
            __syncthreads();
            if (quarter == 0) {
                float4 p0 = buf[jq], p1 = buf[128 + jq], p2 = buf[256 + jq];
                acc.x += zz4.x + p0.x + p1.x + p2.x;
                acc.y += zz4.y + p0.y + p1.y + p2.y;
                acc.z += zz4.z + p0.z + p1.z + p2.z;
                acc.w += zz4.w + p0.w + p1.w + p2.w;
                int gsel = jq >> 5, hh0 = (jq & 31) * 4;
                float4 r;
                if (gsel == 2) {
                    r.x = tanhf(acc.x); r.y = tanhf(acc.y);
                    r.z = tanhf(acc.z); r.w = tanhf(acc.w);
                } else {
                    r.x = sigf(acc.x); r.y = sigf(acc.y);
                    r.z = sigf(acc.z); r.w = sigf(acc.w);
                }
                float* dst = (gsel == 0) ? i_s : (gsel == 1) ? f_s : (gsel == 2) ? gg_s : o_s;
                *(float4*)(dst + hh0) = r;
            }
        }
        __syncthreads();

        // ---- phase 2: s, Jacobian coefficients ----
        if (tid < 128) {
            float iv = i_s[tid], fv = f_s[tid], gv = gg_s[tid], cv = c_sm[tid];
            s_s[tid] = fv * cv + iv * gv;
            ai[tid] = iv * (1.f - iv) * gv;
            af[tid] = fv * (1.f - fv) * cv;
            ag[tid] = iv * (1.f - gv * gv);
        }
        __syncthreads();

        // ---- phase 3: G build, float4 vectorized, all 512 threads ----
        {
            #pragma unroll
            for (int rep = 0; rep < 4; rep++) {
                int q = tid + rep * 512;         // 0..2047
                int h = q >> 4, e4 = (q & 15) * 4;
                float a1 = ai[h], a2 = af[h], a3 = ag[h];
                float4 wi = *(const float4*)(wih + h * 64 + e4);
                float4 wf = *(const float4*)(wih + (128 + h) * 64 + e4);
                float4 wg = *(const float4*)(wih + (256 + h) * 64 + e4);
                float4 g;
                g.x = a1 * wi.x + a2 * wf.x + a3 * wg.x;
                g.y = a1 * wi.y + a2 * wf.y + a3 * wg.y;
                g.z = a1 * wi.z + a2 * wf.z + a3 * wg.z;
                g.w = a1 * wi.w + a2 * wf.w + a3 * wg.w;
                *(float4*)(Gs + h * GS_STRIDE + e4) = g;
            }
        }
        __syncthreads();

        // ---- phase 4: M = I + eps*G^T G (tri 4x2 tiles, f32x2) ; w = G^T s on spare ----
        if (has_tile) {
            int pm = tp_s * 4, qm = tq_s * 2;
            unsigned long long acc[4] = {0ULL, 0ULL, 0ULL, 0ULL};
            for (int h = 0; h < 128; h++) {
                float4 gp = *(const float4*)(Gs + h * GS_STRIDE + pm);
                float2 gq = *(const float2*)(Gs + h * GS_STRIDE + qm);
                unsigned long long q01 = pk2(gq.x, gq.y);
                acc[0] = fma2(pk2(gp.x, gp.x), q01, acc[0]);
                acc[1] = fma2(pk2(gp.y, gp.y), q01, acc[1]);
                acc[2] = fma2(pk2(gp.z, gp.z), q01, acc[2]);
                acc[3] = fma2(pk2(gp.w, gp.w), q01, acc[3]);
            }
            #pragma unroll
            for (int a = 0; a < 4; a++) {
                float m0, m1;
                upk2(acc[a], m0, m1);
                int ri = pm + a;
                float v0 = EPSP * m0 + (ri == qm + 0 ? 1.f : 0.f);
                float v1 = EPSP * m1 + (ri == qm + 1 ? 1.f : 0.f);
                Ms[ri * MS_STRIDE + qm]     = v0;
                Ms[ri * MS_STRIDE + qm + 1] = v1;
                Ms[qm * MS_STRIDE + ri]       = v0;
                Ms[(qm + 1) * MS_STRIDE + ri] = v1;
            }
        } else if (tid >= 272 && tid < 336) {
            int e = tid - 272;
            float acc = 0.f;
            for (int h = 0; h < 128; h++) acc += Gs[h * GS_STRIDE + e] * s_s[h];
            wv[e] = acc;
        }
        __syncthreads();

        // ---- panel LDL^T: phase A register-resident on warp 0 ----
        #pragma unroll 1
        for (int pp = 0; pp < 8; pp++) {
            int p0 = pp * 8;
            if (warp == 0) {
                int row0 = p0 + lane;
                int row1 = p0 + 32 + lane;
                bool act0 = row0 < 64;
                bool act1 = row1 < 64;
                float r0c[8], r1c[8], v0 = 0.f, v1 = 0.f;
                if (act0) {
                    #pragma unroll
                    for (int c = 0; c < 8; c++) r0c[c] = Ms[row0 * MS_STRIDE + p0 + c];
                    v0 = wv[row0];
                }
                if (act1) {
                    #pragma unroll
                    for (int c = 0; c < 8; c++) r1c[c] = Ms[row1 * MS_STRIDE + p0 + c];
                    v1 = wv[row1];
                }
                #pragma unroll
                for (int kl = 0; kl < 8; kl++) {
                    int k = p0 + kl;
                    float dk = __shfl_sync(FULLM, r0c[kl], kl);
                    float vk = __shfl_sync(FULLM, v0, kl);
                    float piv[8];
                    #pragma unroll
                    for (int c = 0; c < 8; c++) piv[c] = __shfl_sync(FULLM, r0c[c], kl);
                    float invd = __fdividef(1.0f, dk);
                    if (lane == kl) { dinv[k] = invd; dval[k] = dk; }
                    if (act0 && row0 > k) {
                        float lv = r0c[kl] * invd;
                        Ln[row0 * MS_STRIDE + k] = lv;
                        v0 -= lv * vk;
                        #pragma unroll
                        for (int c = 0; c < 8; c++) if (c > kl) r0c[c] -= lv * piv[c];
                    }
                    if (act1) {
                        float lv = r1c[kl] * invd;
                        Ln[row1 * MS_STRIDE + k] = lv;
                        v1 -= lv * vk;
                        #pragma unroll
                        for (int c = 0; c < 8; c++) if (c > kl) r1c[c] -= lv * piv[c];
                    }
                }
                if (act0) wv[row0] = v0;
                if (act1) wv[row1] = v1;
            }
            __syncthreads();

            // phase B: rank-8 trailing update (16 warps)
            int r0 = p0 + 8;
            if (r0 < 64) {
                for (int jq = warp; jq * 4 < 64 - r0; jq += 16) {
                    int jb = r0 + jq * 4;
                    float lrd[4][8];
                    #pragma unroll
                    for (int u = 0; u < 4; u++)
                        #pragma unroll
                        for (int c = 0; c < 8; c++)
                            lrd[u][c] = Ln[(jb + u) * MS_STRIDE + p0 + c] * dval[p0 + c];
                    for (int i = r0 + lane; i < 64; i += 32) {
                        float a[8];
                        #pragma unroll
                        for (int c = 0; c < 8; c++) a[c] = Ln[i * MS_STRIDE + p0 + c];
                        #pragma unroll
                        for (int u = 0; u < 4; u++) {
                            int j = jb + u;
                            float acc = Ms[j * MS_STRIDE + i];
                            #pragma unroll
                            for (int c = 0; c < 8; c++) acc -= lrd[u][c] * a[c];
                            Ms[j * MS_STRIDE + i] = acc;
                        }
                    }
                }
                __syncthreads();
            }
        }

        // ---- back solve (warp 0, register-resident) ----
        if (warp == 0) {
            float x0 = wv[lane] * dinv[lane];
            float x1 = wv[lane + 32] * dinv[lane + 32];
            #pragma unroll 1
            for (int k = 63; k >= 32; k--) {
                float xk = __shfl_sync(FULLM, x1, k - 32);
                if (lane + 32 < k) x1 -= Ln[k * MS_STRIDE + lane + 32] * xk;
                x0 -= Ln[k * MS_STRIDE + lane] * xk;
            }
            #pragma unroll 1
            for (int k = 31; k >= 1; k--) {
                float xk = __shfl_sync(FULLM, x0, k);
                if (lane < k) x0 -= Ln[k * MS_STRIDE + lane] * xk;
            }
            wv[lane] = x0;
            wv[lane + 32] = x1;
        }
        __syncthreads();

        // ---- epilogue: c = s - eps*G*x ; h = o*tanh(c) ----
        if (tid < 128) {
            const float4* gr = (const float4*)(Gs + tid * GS_STRIDE);
            const float4* wr = (const float4*)wv;
            float acc = 0.f;
            #pragma unroll
            for (int q = 0; q < 16; q++) {
                float4 g4 = gr[q];
                float4 w4 = wr[q];
                acc += g4.x * w4.x + g4.y * w4.y + g4.z * w4.z + g4.w * w4.w;
            }
            float cn = s_s[tid] - EPSP * acc;
            c_sm[tid] = cn;
            h_sm[tid] = o_s[tid] * tanhf(cn);
        }
        __syncthreads();
    }

    if (tid < ODIM) {
        float acc = lin_b[tid];
        for (int k = 0; k < 128; k++) acc += h_sm[k] * lin_w[tid * 128 + k];
        out[b * ODIM + tid] = acc;
    }
}

extern "C" void kernel_launch(void* const* d_in, const int* in_sizes, int n_in,
                              void* d_out, int out_size) {
    const float* inputs  = (const float*)d_in[0];
    const float* conv_w  = (const float*)d_in[2];
    const float* conv_b  = (const float*)d_in[3];
    const float* bn_g    = (const float*)d_in[4];
    const float* bn_b    = (const float*)d_in[5];
    const float* w_ih    = (const float*)d_in[6];
    const float* w_hh    = (const float*)d_in[7];
    const float* b_ih    = (const float*)d_in[8];
    const float* b_hh    = (const float*)d_in[9];
    const float* lin_w   = (const float*)d_in[10];
    const float* lin_b   = (const float*)d_in[11];
    float* out = (float*)d_out;

    cudaFuncSetAttribute(k4_scan, cudaFuncAttributeMaxDynamicSharedMemorySize, 73984);

    k0_prep<<<483, 256>>>(w_ih, w_hh, b_ih, b_hh, conv_w);
    k1_conv<<<1024, 256>>>(inputs, conv_b);
    k2a_stats<<<256, 256>>>();
    k2b_finalize<<<1, 64>>>(bn_g, bn_b);
    k3_zx<<<2048, 256>>>();
    k4_scan<<<64, 512, 73984>>>(lin_w, lin_b, w_ih, out);
}